// round 6
// baseline (speedup 1.0000x reference)
#include <cuda_runtime.h>
#include <cstdint>

#define SLEN 1024
#define BSZ  16
#define IND  256
#define NH   8
#define DH   32
#define PROJ 776              // NH*(3*DH+1)
#define NTOK (SLEN*BSZ)       // 16384
#define NCHAIN (BSZ*NH)       // 128
#define FW_ELEMS (NCHAIN*DH*DH)
#define TC   16               // time steps staged per smem refill
#define NCHUNK (SLEN/4)       // 4-step WY chunks per chain

// Scratch (static device globals; no runtime allocation)
__device__ float g_normed[(size_t)NTOK*IND];
__device__ float g_qkvb[(size_t)NTOK*PROJ];
__device__ float g_oseq[(size_t)NTOK*IND];
// chain-major prepped streams: [chain][t][lane]
__device__ float g_kn[(size_t)NCHAIN*SLEN*DH];
__device__ float g_qn[(size_t)NCHAIN*SLEN*DH];
__device__ float g_vn[(size_t)NCHAIN*SLEN*DH];
__device__ float g_sc[(size_t)NCHAIN*SLEN*2];        // (beta, k.q) per step
// WY cross terms per 4-step chunk: [chain][chunk][16]
//   [0..9]  k_i . q_j  for (i,j) in (00,01,02,03,11,12,13,22,23,33)
//   [10..15] -beta_j * (k_i . k_j) for (01,02,03,12,13,23)
__device__ float g_cross[(size_t)NCHAIN*NCHUNK*16];

// ---------------------------------------------------------------------------
// Packed f32x2 helpers (Blackwell)
// ---------------------------------------------------------------------------
typedef unsigned long long u64t;

__device__ __forceinline__ u64t f2pack(float lo, float hi) {
    u64t r;
    asm("mov.b64 %0, {%1, %2};" : "=l"(r) : "f"(lo), "f"(hi));
    return r;
}
__device__ __forceinline__ void f2unpack(u64t v, float& lo, float& hi) {
    asm("mov.b64 {%0, %1}, %2;" : "=f"(lo), "=f"(hi) : "l"(v));
}
__device__ __forceinline__ u64t ffma2(u64t a, u64t b, u64t c) {
    u64t d;
    asm("fma.rn.f32x2 %0, %1, %2, %3;" : "=l"(d) : "l"(a), "l"(b), "l"(c));
    return d;
}

// 8-wide dot of packed slices (4 x f32x2)
__device__ __forceinline__ float dot8(const u64t* __restrict__ Wp,
                                      const u64t* __restrict__ vp) {
    u64t a = 0ull, b = 0ull;
    a = ffma2(Wp[0], vp[0], a); b = ffma2(Wp[1], vp[1], b);
    a = ffma2(Wp[2], vp[2], a); b = ffma2(Wp[3], vp[3], b);
    float x0, x1, y0, y1;
    f2unpack(a, x0, x1); f2unpack(b, y0, y1);
    return (x0 + y0) + (x1 + y1);
}

// ---------------------------------------------------------------------------
// LayerNorm: one block (256 threads) per token row
// ---------------------------------------------------------------------------
__global__ void ln_kernel(const float* __restrict__ x,
                          const float* __restrict__ gamma,
                          const float* __restrict__ beta)
{
    int row = blockIdx.x;
    int tid = threadIdx.x;
    float v = x[(size_t)row * IND + tid];
    float s = v, s2 = v * v;
#pragma unroll
    for (int o = 16; o > 0; o >>= 1) {
        s  += __shfl_xor_sync(0xffffffffu, s,  o);
        s2 += __shfl_xor_sync(0xffffffffu, s2, o);
    }
    __shared__ float sh[2][8];
    int w = tid >> 5, l = tid & 31;
    if (l == 0) { sh[0][w] = s; sh[1][w] = s2; }
    __syncthreads();
    float ts = 0.f, ts2 = 0.f;
#pragma unroll
    for (int i = 0; i < 8; i++) { ts += sh[0][i]; ts2 += sh[1][i]; }
    float mu  = ts * (1.0f / IND);
    float var = ts2 * (1.0f / IND) - mu * mu;
    float r   = rsqrtf(var + 1e-5f);
    g_normed[(size_t)row * IND + tid] = (v - mu) * r * gamma[tid] + beta[tid];
}

// ---------------------------------------------------------------------------
// Prep: elu+1, sum-norm, sigmoid(beta), k.q — chain-major. One warp / (t,chain)
// ---------------------------------------------------------------------------
__global__ __launch_bounds__(256)
void prep_kernel()
{
    int gw   = blockIdx.x * 8 + (threadIdx.x >> 5);
    int lane = threadIdx.x & 31;
    int t    = gw >> 7;
    int ch   = gw & 127;
    int b    = ch >> 3, h = ch & 7;

    const float* base = g_qkvb + ((size_t)t * BSZ + b) * PROJ + h * 97;
    float q = base[lane], k = base[32 + lane], v = base[64 + lane], bta = base[96];

    float eq = q > 0.f ? q + 1.f : __expf(q);
    float ek = k > 0.f ? k + 1.f : __expf(k);
    float sq = eq, sk = ek, sqk = eq * ek;
#pragma unroll
    for (int o = 16; o > 0; o >>= 1) {
        sq  += __shfl_xor_sync(0xffffffffu, sq,  o);
        sk  += __shfl_xor_sync(0xffffffffu, sk,  o);
        sqk += __shfl_xor_sync(0xffffffffu, sqk, o);
    }
    float rsq = 1.0f / (sq + 1e-5f);
    float rsk = 1.0f / (sk + 1e-5f);

    size_t o_idx = ((size_t)ch * SLEN + t) * DH + lane;
    g_qn[o_idx] = eq * rsq;
    g_kn[o_idx] = ek * rsk;
    g_vn[o_idx] = v;
    if (lane == 0) {
        size_t si = ((size_t)ch * SLEN + t) * 2;
        g_sc[si]     = 1.0f / (1.0f + __expf(-bta));
        g_sc[si + 1] = sqk * rsq * rsk;
    }
}

// ---------------------------------------------------------------------------
// Prep2: WY cross terms per 4-step chunk. One warp per (chain, chunk).
// ---------------------------------------------------------------------------
__global__ __launch_bounds__(256)
void prep2_kernel()
{
    int gw   = blockIdx.x * 8 + (threadIdx.x >> 5);   // 0 .. NCHAIN*NCHUNK-1
    int lane = threadIdx.x & 31;
    int ch   = gw >> 8;          // chain
    int cu   = gw & 255;         // chunk
    int t0   = cu * 4;

    const float* kb = g_kn + ((size_t)ch * SLEN + t0) * DH;
    const float* qb = g_qn + ((size_t)ch * SLEN + t0) * DH;
    float k0 = kb[lane], k1 = kb[DH + lane], k2 = kb[2 * DH + lane], k3 = kb[3 * DH + lane];
    float q0 = qb[lane], q1 = qb[DH + lane], q2 = qb[2 * DH + lane], q3 = qb[3 * DH + lane];

    float r[16];
    r[0]  = k0 * q0; r[1]  = k0 * q1; r[2]  = k0 * q2; r[3]  = k0 * q3;
    r[4]  = k1 * q1; r[5]  = k1 * q2; r[6]  = k1 * q3;
    r[7]  = k2 * q2; r[8]  = k2 * q3; r[9]  = k3 * q3;
    r[10] = k0 * k1; r[11] = k0 * k2; r[12] = k0 * k3;
    r[13] = k1 * k2; r[14] = k1 * k3; r[15] = k2 * k3;
#pragma unroll
    for (int o = 16; o > 0; o >>= 1) {
#pragma unroll
        for (int i = 0; i < 16; i++)
            r[i] += __shfl_xor_sync(0xffffffffu, r[i], o);
    }

    const float* sc = g_sc + ((size_t)ch * SLEN + t0) * 2;
    float b1 = sc[2], b2 = sc[4], b3 = sc[6];
    r[10] *= -b1; r[11] *= -b2; r[12] *= -b3;
    r[13] *= -b2; r[14] *= -b3; r[15] *= -b3;

    if (lane == 0) {
        float4* o = (float4*)(g_cross + ((size_t)ch * NCHUNK + cu) * 16);
        o[0] = make_float4(r[0],  r[1],  r[2],  r[3]);
        o[1] = make_float4(r[4],  r[5],  r[6],  r[7]);
        o[2] = make_float4(r[8],  r[9],  r[10], r[11]);
        o[3] = make_float4(r[12], r[13], r[14], r[15]);
    }
}

// ---------------------------------------------------------------------------
// Tiled NT GEMM: C[M,N] = A[M,K]*B[N,K]^T (+resid), f32x2 FMA,
// double-buffered smem, register-staged loads.
// ---------------------------------------------------------------------------
#define BM 128
#define BN 128
#define BK 16
#define LDS_PAD 132

__global__ __launch_bounds__(256)
void gemm_nt(const float* __restrict__ A, const float* __restrict__ B,
             float* __restrict__ C, int M, int N, int K,
             const float* __restrict__ resid)
{
    __shared__ __align__(16) float As[2][BK][LDS_PAD];
    __shared__ __align__(16) float Bs[2][BK][LDS_PAD];

    int bm = blockIdx.x * BM;
    int bn = blockIdx.y * BN;
    int tid = threadIdx.x;
    int tx = tid & 15, ty = tid >> 4;
    int m0 = ty * 8, n0 = tx * 8;

    int f0 = tid,       r0 = f0 >> 2, kq0 = (f0 & 3) * 4;
    int f1 = tid + 256, r1 = f1 >> 2, kq1 = (f1 & 3) * 4;

    float4 va0, va1, vb0, vb1;

    auto LOAD = [&](int k0) {
        va0 = *(const float4*)(A + (size_t)(bm + r0) * K + k0 + kq0);
        va1 = *(const float4*)(A + (size_t)(bm + r1) * K + k0 + kq1);
        vb0 = make_float4(0.f, 0.f, 0.f, 0.f);
        vb1 = make_float4(0.f, 0.f, 0.f, 0.f);
        if (bn + r0 < N) vb0 = *(const float4*)(B + (size_t)(bn + r0) * K + k0 + kq0);
        if (bn + r1 < N) vb1 = *(const float4*)(B + (size_t)(bn + r1) * K + k0 + kq1);
    };
    auto STORE = [&](int buf) {
        As[buf][kq0 + 0][r0] = va0.x; As[buf][kq0 + 1][r0] = va0.y;
        As[buf][kq0 + 2][r0] = va0.z; As[buf][kq0 + 3][r0] = va0.w;
        As[buf][kq1 + 0][r1] = va1.x; As[buf][kq1 + 1][r1] = va1.y;
        As[buf][kq1 + 2][r1] = va1.z; As[buf][kq1 + 3][r1] = va1.w;
        Bs[buf][kq0 + 0][r0] = vb0.x; Bs[buf][kq0 + 1][r0] = vb0.y;
        Bs[buf][kq0 + 2][r0] = vb0.z; Bs[buf][kq0 + 3][r0] = vb0.w;
        Bs[buf][kq1 + 0][r1] = vb1.x; Bs[buf][kq1 + 1][r1] = vb1.y;
        Bs[buf][kq1 + 2][r1] = vb1.z; Bs[buf][kq1 + 3][r1] = vb1.w;
    };

    u64t acc[8][4];
#pragma unroll
    for (int i = 0; i < 8; i++)
#pragma unroll
        for (int j = 0; j < 4; j++) acc[i][j] = 0ull;

    LOAD(0); STORE(0);
    __syncthreads();

    int nk = K / BK;
    for (int kt = 0; kt < nk; kt++) {
        int cur = kt & 1;
        if (kt + 1 < nk) LOAD((kt + 1) * BK);

#pragma unroll
        for (int kk = 0; kk < BK; kk++) {
            float4 a0 = *(const float4*)&As[cur][kk][m0];
            float4 a1 = *(const float4*)&As[cur][kk][m0 + 4];
            const u64t* bp = (const u64t*)&Bs[cur][kk][n0];
            u64t b0 = bp[0], b1 = bp[1], b2 = bp[2], b3 = bp[3];

            u64t as[8];
            as[0] = f2pack(a0.x, a0.x); as[1] = f2pack(a0.y, a0.y);
            as[2] = f2pack(a0.z, a0.z); as[3] = f2pack(a0.w, a0.w);
            as[4] = f2pack(a1.x, a1.x); as[5] = f2pack(a1.y, a1.y);
            as[6] = f2pack(a1.z, a1.z); as[7] = f2pack(a1.w, a1.w);
#pragma unroll
            for (int i = 0; i < 8; i++) {
                acc[i][0] = ffma2(as[i], b0, acc[i][0]);
                acc[i][1] = ffma2(as[i], b1, acc[i][1]);
                acc[i][2] = ffma2(as[i], b2, acc[i][2]);
                acc[i][3] = ffma2(as[i], b3, acc[i][3]);
            }
        }

        if (kt + 1 < nk) STORE(cur ^ 1);
        __syncthreads();
    }

#pragma unroll
    for (int i = 0; i < 8; i++) {
        int m = bm + m0 + i;
#pragma unroll
        for (int j = 0; j < 4; j++) {
            float c0, c1;
            f2unpack(acc[i][j], c0, c1);
            int n = bn + n0 + 2 * j;
            if (n < N) {
                float v0 = c0;
                if (resid) v0 += resid[(size_t)m * N + n];
                C[(size_t)m * N + n] = v0;
            }
            if (n + 1 < N) {
                float v1 = c1;
                if (resid) v1 += resid[(size_t)m * N + n + 1];
                C[(size_t)m * N + n + 1] = v1;
            }
        }
    }
}

// ---------------------------------------------------------------------------
// Delta-rule recurrence, WY-chunked, 4 WARPS PER CHAIN (column-split W).
// Thread (r, g): row r, columns [8g, 8g+8) of the 32x32 fast-weight matrix.
// Per 4-step chunk: partial dots -> smem -> 1 barrier -> redundant per-row
// delta/output chain in all warps (no 2nd barrier) -> local rank-4 update.
// part[] is double-buffered across chunks so one barrier per chunk suffices.
// ---------------------------------------------------------------------------
__global__ __launch_bounds__(128)
void rec_kernel(const float* __restrict__ state,
                float* __restrict__ out_fw, int write_fw)
{
    int chain = blockIdx.x;            // 0..127
    int b = chain >> 3, h = chain & 7;
    int tid = threadIdx.x;
    int r = tid & 31;                  // row
    int g = tid >> 5;                  // column group (warp id)

    u64t Wp[4];
    const u64t* st = (const u64t*)(state + ((size_t)chain * DH + r) * DH + g * 8);
#pragma unroll
    for (int j = 0; j < 4; j++) Wp[j] = st[j];

    __shared__ __align__(16) float sk[2][TC * DH];
    __shared__ __align__(16) float sq[2][TC * DH];
    __shared__ __align__(16) float sv[2][TC * DH];
    __shared__ __align__(16) float sb_[2][TC * 2];
    __shared__ __align__(16) float scr[2][(TC / 4) * 16];
    __shared__ float part[2][8][32][5];   // [pbuf][s(0-3:A,4-7:Q)][row][g] padded

    const float* kb  = g_kn + (size_t)chain * SLEN * DH;
    const float* qb  = g_qn + (size_t)chain * SLEN * DH;
    const float* vb  = g_vn + (size_t)chain * SLEN * DH;
    const float* sbp = g_sc + (size_t)chain * SLEN * 2;
    const float* crb = g_cross + (size_t)chain * NCHUNK * 16;

    auto REFILL = [&](int cc, int buf) {
        const float4* kp = (const float4*)(kb + (size_t)cc * TC * DH);
        const float4* qp = (const float4*)(qb + (size_t)cc * TC * DH);
        const float4* vp = (const float4*)(vb + (size_t)cc * TC * DH);
        ((float4*)sk[buf])[tid] = kp[tid];
        ((float4*)sq[buf])[tid] = qp[tid];
        ((float4*)sv[buf])[tid] = vp[tid];
        if (tid < TC * 2) sb_[buf][tid] = sbp[cc * TC * 2 + tid];
        if (tid < 64)     scr[buf][tid] = crb[cc * 64 + tid];
    };

    REFILL(0, 0);
    __syncthreads();

    const int NCC = SLEN / TC;
    for (int cc = 0; cc < NCC; cc++) {
        int buf = cc & 1;
        if (cc + 1 < NCC) REFILL(cc + 1, buf ^ 1);

#pragma unroll
        for (int q4 = 0; q4 < TC / 4; q4++) {
            int tb = q4 * 4;
            int pc = (cc * (TC / 4) + q4) & 1;

            // per-thread 8-wide slices of k_s (kept for the update)
            u64t ks[4][4];
#pragma unroll
            for (int s = 0; s < 4; s++) {
                const u64t* kp = (const u64t*)&sk[buf][(tb + s) * DH + g * 8];
#pragma unroll
                for (int j = 0; j < 4; j++) ks[s][j] = kp[j];
            }

            // partial dots vs this thread's W slice
#pragma unroll
            for (int s = 0; s < 4; s++) {
                const u64t* qp = (const u64t*)&sq[buf][(tb + s) * DH + g * 8];
                part[pc][s][r][g]     = dot8(Wp, ks[s]);
                part[pc][s + 4][r][g] = dot8(Wp, qp);
            }
            __syncthreads();

            // redundant per-row reduction + WY chain (all 4 warps)
            float A0 = part[pc][0][r][0] + part[pc][0][r][1] + part[pc][0][r][2] + part[pc][0][r][3];
            float A1 = part[pc][1][r][0] + part[pc][1][r][1] + part[pc][1][r][2] + part[pc][1][r][3];
            float A2 = part[pc][2][r][0] + part[pc][2][r][1] + part[pc][2][r][2] + part[pc][2][r][3];
            float A3 = part[pc][3][r][0] + part[pc][3][r][1] + part[pc][3][r][2] + part[pc][3][r][3];
            float Q0 = part[pc][4][r][0] + part[pc][4][r][1] + part[pc][4][r][2] + part[pc][4][r][3];
            float Q1 = part[pc][5][r][0] + part[pc][5][r][1] + part[pc][5][r][2] + part[pc][5][r][3];
            float Q2 = part[pc][6][r][0] + part[pc][6][r][1] + part[pc][6][r][2] + part[pc][6][r][3];
            float Q3 = part[pc][7][r][0] + part[pc][7][r][1] + part[pc][7][r][2] + part[pc][7][r][3];

            float be0 = sb_[buf][(tb + 0) * 2], be1 = sb_[buf][(tb + 1) * 2];
            float be2 = sb_[buf][(tb + 2) * 2], be3 = sb_[buf][(tb + 3) * 2];
            float vv0 = sv[buf][(tb + 0) * DH + r];
            float vv1 = sv[buf][(tb + 1) * DH + r];
            float vv2 = sv[buf][(tb + 2) * DH + r];
            float vv3 = sv[buf][(tb + 3) * DH + r];
            const float* cr = &scr[buf][q4 * 16];

            float d0 = fmaf(-be0, A0, be0 * vv0);
            float p1 = fmaf(-be1, A1, be1 * vv1);
            float p2 = fmaf(-be2, A2, be2 * vv2);
            float p3 = fmaf(-be3, A3, be3 * vv3);
            float d1 = fmaf(d0, cr[10], p1);
            float d2 = fmaf(d1, cr[13], fmaf(d0, cr[11], p2));
            float d3 = fmaf(d2, cr[15], fmaf(d1, cr[14], fmaf(d0, cr[12], p3)));

            // outputs: warp g stores o_g (one STG per thread per chunk)
            float og;
            if (g == 0)      og = fmaf(d0, cr[0], Q0);
            else if (g == 1) og = fmaf(d1, cr[4], fmaf(d0, cr[1], Q1));
            else if (g == 2) og = fmaf(d2, cr[7], fmaf(d1, cr[5], fmaf(d0, cr[2], Q2)));
            else             og = fmaf(d3, cr[9], fmaf(d2, cr[8], fmaf(d1, cr[6], fmaf(d0, cr[3], Q3))));

            int t = cc * TC + tb + g;
            g_oseq[((size_t)t * BSZ + b) * IND + h * DH + r] = og;

            // local rank-4 update on this thread's 8-column slice
            u64t D0 = f2pack(d0, d0), D1 = f2pack(d1, d1);
            u64t D2 = f2pack(d2, d2), D3 = f2pack(d3, d3);
#pragma unroll
            for (int j = 0; j < 4; j++) {
                u64t w = Wp[j];
                w = ffma2(D0, ks[0][j], w);
                w = ffma2(D1, ks[1][j], w);
                w = ffma2(D2, ks[2][j], w);
                w = ffma2(D3, ks[3][j], w);
                Wp[j] = w;
            }
        }
    }

    if (write_fw) {
        u64t* fw = (u64t*)(out_fw + ((size_t)chain * DH + r) * DH + g * 8);
#pragma unroll
        for (int j = 0; j < 4; j++) fw[j] = Wp[j];
    }
}

// ---------------------------------------------------------------------------
extern "C" void kernel_launch(void* const* d_in, const int* in_sizes, int n_in,
                              void* d_out, int out_size)
{
    const float* x        = (const float*)d_in[0];
    const float* state    = (const float*)d_in[1];
    const float* W_slow   = (const float*)d_in[2];
    const float* ln_gamma = (const float*)d_in[3];
    const float* ln_beta  = (const float*)d_in[4];
    const float* W_out    = (const float*)d_in[5];
    float* out = (float*)d_out;

    float* normed; cudaGetSymbolAddress((void**)&normed, g_normed);
    float* qkvb;   cudaGetSymbolAddress((void**)&qkvb,   g_qkvb);
    float* oseq;   cudaGetSymbolAddress((void**)&oseq,   g_oseq);

    // 1) LayerNorm
    ln_kernel<<<NTOK, IND>>>(x, ln_gamma, ln_beta);

    // 2) qkvb = normed @ W_slow^T   [16384 x 776]
    dim3 gB(NTOK / BM, (PROJ + BN - 1) / BN);
    gemm_nt<<<gB, 256>>>(normed, W_slow, qkvb, NTOK, PROJ, IND, nullptr);

    // 3) prep: activations + normalizers + beta + k.q, chain-major
    prep_kernel<<<SLEN * NCHAIN / 8, 256>>>();

    // 3b) prep2: WY cross terms per 4-step chunk
    prep2_kernel<<<NCHAIN * NCHUNK / 8, 256>>>();

    // 4) delta-rule recurrence (WY-chunked, 4 warps/chain)
    int write_fw = (out_size >= (int)((size_t)NTOK * IND + FW_ELEMS)) ? 1 : 0;
    rec_kernel<<<NCHAIN, 128>>>(state, out + (size_t)NTOK * IND, write_fw);

    // 5) out = x + oseq @ W_out^T   [16384 x 256]
    dim3 gD(NTOK / BM, (IND + BN - 1) / BN);
    gemm_nt<<<gD, 256>>>(oseq, W_out, out, NTOK, IND, IND, x);
}

// round 7
// speedup vs baseline: 1.5626x; 1.5626x over previous
#include <cuda_runtime.h>
#include <cstdint>

#define SLEN 1024
#define BSZ  16
#define IND  256
#define NH   8
#define DH   32
#define PROJ 776              // NH*(3*DH+1)
#define NTOK (SLEN*BSZ)       // 16384
#define NCHAIN (BSZ*NH)       // 128
#define FW_ELEMS (NCHAIN*DH*DH)
#define TC   16               // time steps staged per smem refill
#define NCHUNK (SLEN/4)       // 4-step WY chunks per chain

// Scratch (static device globals; no runtime allocation)
__device__ float g_normed[(size_t)NTOK*IND];
__device__ float g_qkvb[(size_t)NTOK*PROJ];
__device__ float g_oseq[(size_t)NTOK*IND];
// chain-major prepped streams: [chain][t][lane]
__device__ float g_kn[(size_t)NCHAIN*SLEN*DH];
__device__ float g_qn[(size_t)NCHAIN*SLEN*DH];
__device__ float g_vn[(size_t)NCHAIN*SLEN*DH];
__device__ float g_sc[(size_t)NCHAIN*SLEN*2];        // (beta, k.q) per step
// WY cross terms per 4-step chunk: [chain][chunk][16]
//   [0..9]  k_i . q_j  for (i,j) in (00,01,02,03,11,12,13,22,23,33)
//   [10..15] -beta_j * (k_i . k_j) for (01,02,03,12,13,23)
__device__ float g_cross[(size_t)NCHAIN*NCHUNK*16];

// ---------------------------------------------------------------------------
// Packed f32x2 helpers (Blackwell)
// ---------------------------------------------------------------------------
typedef unsigned long long u64t;

__device__ __forceinline__ u64t f2pack(float lo, float hi) {
    u64t r;
    asm("mov.b64 %0, {%1, %2};" : "=l"(r) : "f"(lo), "f"(hi));
    return r;
}
__device__ __forceinline__ void f2unpack(u64t v, float& lo, float& hi) {
    asm("mov.b64 {%0, %1}, %2;" : "=f"(lo), "=f"(hi) : "l"(v));
}
__device__ __forceinline__ u64t ffma2(u64t a, u64t b, u64t c) {
    u64t d;
    asm("fma.rn.f32x2 %0, %1, %2, %3;" : "=l"(d) : "l"(a), "l"(b), "l"(c));
    return d;
}

// 8-wide dot of packed slices (4 x f32x2)
__device__ __forceinline__ float dot8(const u64t* __restrict__ Wp,
                                      const u64t* __restrict__ vp) {
    u64t a = 0ull, b = 0ull;
    a = ffma2(Wp[0], vp[0], a); b = ffma2(Wp[1], vp[1], b);
    a = ffma2(Wp[2], vp[2], a); b = ffma2(Wp[3], vp[3], b);
    float x0, x1, y0, y1;
    f2unpack(a, x0, x1); f2unpack(b, y0, y1);
    return (x0 + y0) + (x1 + y1);
}

// ---------------------------------------------------------------------------
// LayerNorm: one block (256 threads) per token row
// ---------------------------------------------------------------------------
__global__ void ln_kernel(const float* __restrict__ x,
                          const float* __restrict__ gamma,
                          const float* __restrict__ beta)
{
    int row = blockIdx.x;
    int tid = threadIdx.x;
    float v = x[(size_t)row * IND + tid];
    float s = v, s2 = v * v;
#pragma unroll
    for (int o = 16; o > 0; o >>= 1) {
        s  += __shfl_xor_sync(0xffffffffu, s,  o);
        s2 += __shfl_xor_sync(0xffffffffu, s2, o);
    }
    __shared__ float sh[2][8];
    int w = tid >> 5, l = tid & 31;
    if (l == 0) { sh[0][w] = s; sh[1][w] = s2; }
    __syncthreads();
    float ts = 0.f, ts2 = 0.f;
#pragma unroll
    for (int i = 0; i < 8; i++) { ts += sh[0][i]; ts2 += sh[1][i]; }
    float mu  = ts * (1.0f / IND);
    float var = ts2 * (1.0f / IND) - mu * mu;
    float r   = rsqrtf(var + 1e-5f);
    g_normed[(size_t)row * IND + tid] = (v - mu) * r * gamma[tid] + beta[tid];
}

// ---------------------------------------------------------------------------
// Prep: elu+1, sum-norm, sigmoid(beta), k.q — chain-major. One warp / (t,chain)
// ---------------------------------------------------------------------------
__global__ __launch_bounds__(256)
void prep_kernel()
{
    int gw   = blockIdx.x * 8 + (threadIdx.x >> 5);
    int lane = threadIdx.x & 31;
    int t    = gw >> 7;
    int ch   = gw & 127;
    int b    = ch >> 3, h = ch & 7;

    const float* base = g_qkvb + ((size_t)t * BSZ + b) * PROJ + h * 97;
    float q = base[lane], k = base[32 + lane], v = base[64 + lane], bta = base[96];

    float eq = q > 0.f ? q + 1.f : __expf(q);
    float ek = k > 0.f ? k + 1.f : __expf(k);
    float sq = eq, sk = ek, sqk = eq * ek;
#pragma unroll
    for (int o = 16; o > 0; o >>= 1) {
        sq  += __shfl_xor_sync(0xffffffffu, sq,  o);
        sk  += __shfl_xor_sync(0xffffffffu, sk,  o);
        sqk += __shfl_xor_sync(0xffffffffu, sqk, o);
    }
    float rsq = 1.0f / (sq + 1e-5f);
    float rsk = 1.0f / (sk + 1e-5f);

    size_t o_idx = ((size_t)ch * SLEN + t) * DH + lane;
    g_qn[o_idx] = eq * rsq;
    g_kn[o_idx] = ek * rsk;
    g_vn[o_idx] = v;
    if (lane == 0) {
        size_t si = ((size_t)ch * SLEN + t) * 2;
        g_sc[si]     = 1.0f / (1.0f + __expf(-bta));
        g_sc[si + 1] = sqk * rsq * rsk;
    }
}

// ---------------------------------------------------------------------------
// Prep2: WY cross terms per 4-step chunk. One warp per (chain, chunk).
// ---------------------------------------------------------------------------
__global__ __launch_bounds__(256)
void prep2_kernel()
{
    int gw   = blockIdx.x * 8 + (threadIdx.x >> 5);   // 0 .. NCHAIN*NCHUNK-1
    int lane = threadIdx.x & 31;
    int ch   = gw >> 8;          // chain
    int cu   = gw & 255;         // chunk
    int t0   = cu * 4;

    const float* kb = g_kn + ((size_t)ch * SLEN + t0) * DH;
    const float* qb = g_qn + ((size_t)ch * SLEN + t0) * DH;
    float k0 = kb[lane], k1 = kb[DH + lane], k2 = kb[2 * DH + lane], k3 = kb[3 * DH + lane];
    float q0 = qb[lane], q1 = qb[DH + lane], q2 = qb[2 * DH + lane], q3 = qb[3 * DH + lane];

    float r[16];
    r[0]  = k0 * q0; r[1]  = k0 * q1; r[2]  = k0 * q2; r[3]  = k0 * q3;
    r[4]  = k1 * q1; r[5]  = k1 * q2; r[6]  = k1 * q3;
    r[7]  = k2 * q2; r[8]  = k2 * q3; r[9]  = k3 * q3;
    r[10] = k0 * k1; r[11] = k0 * k2; r[12] = k0 * k3;
    r[13] = k1 * k2; r[14] = k1 * k3; r[15] = k2 * k3;
#pragma unroll
    for (int o = 16; o > 0; o >>= 1) {
#pragma unroll
        for (int i = 0; i < 16; i++)
            r[i] += __shfl_xor_sync(0xffffffffu, r[i], o);
    }

    const float* sc = g_sc + ((size_t)ch * SLEN + t0) * 2;
    float b1 = sc[2], b2 = sc[4], b3 = sc[6];
    r[10] *= -b1; r[11] *= -b2; r[12] *= -b3;
    r[13] *= -b2; r[14] *= -b3; r[15] *= -b3;

    if (lane == 0) {
        float4* o = (float4*)(g_cross + ((size_t)ch * NCHUNK + cu) * 16);
        o[0] = make_float4(r[0],  r[1],  r[2],  r[3]);
        o[1] = make_float4(r[4],  r[5],  r[6],  r[7]);
        o[2] = make_float4(r[8],  r[9],  r[10], r[11]);
        o[3] = make_float4(r[12], r[13], r[14], r[15]);
    }
}

// ---------------------------------------------------------------------------
// Tiled NT GEMM: C[M,N] = A[M,K]*B[N,K]^T (+resid), f32x2 FMA,
// double-buffered smem, register-staged loads.
// ---------------------------------------------------------------------------
#define BM 128
#define BN 128
#define BK 16
#define LDS_PAD 132

__global__ __launch_bounds__(256)
void gemm_nt(const float* __restrict__ A, const float* __restrict__ B,
             float* __restrict__ C, int M, int N, int K,
             const float* __restrict__ resid)
{
    __shared__ __align__(16) float As[2][BK][LDS_PAD];
    __shared__ __align__(16) float Bs[2][BK][LDS_PAD];

    int bm = blockIdx.x * BM;
    int bn = blockIdx.y * BN;
    int tid = threadIdx.x;
    int tx = tid & 15, ty = tid >> 4;
    int m0 = ty * 8, n0 = tx * 8;

    int f0 = tid,       r0 = f0 >> 2, kq0 = (f0 & 3) * 4;
    int f1 = tid + 256, r1 = f1 >> 2, kq1 = (f1 & 3) * 4;

    float4 va0, va1, vb0, vb1;

    auto LOAD = [&](int k0) {
        va0 = *(const float4*)(A + (size_t)(bm + r0) * K + k0 + kq0);
        va1 = *(const float4*)(A + (size_t)(bm + r1) * K + k0 + kq1);
        vb0 = make_float4(0.f, 0.f, 0.f, 0.f);
        vb1 = make_float4(0.f, 0.f, 0.f, 0.f);
        if (bn + r0 < N) vb0 = *(const float4*)(B + (size_t)(bn + r0) * K + k0 + kq0);
        if (bn + r1 < N) vb1 = *(const float4*)(B + (size_t)(bn + r1) * K + k0 + kq1);
    };
    auto STORE = [&](int buf) {
        As[buf][kq0 + 0][r0] = va0.x; As[buf][kq0 + 1][r0] = va0.y;
        As[buf][kq0 + 2][r0] = va0.z; As[buf][kq0 + 3][r0] = va0.w;
        As[buf][kq1 + 0][r1] = va1.x; As[buf][kq1 + 1][r1] = va1.y;
        As[buf][kq1 + 2][r1] = va1.z; As[buf][kq1 + 3][r1] = va1.w;
        Bs[buf][kq0 + 0][r0] = vb0.x; Bs[buf][kq0 + 1][r0] = vb0.y;
        Bs[buf][kq0 + 2][r0] = vb0.z; Bs[buf][kq0 + 3][r0] = vb0.w;
        Bs[buf][kq1 + 0][r1] = vb1.x; Bs[buf][kq1 + 1][r1] = vb1.y;
        Bs[buf][kq1 + 2][r1] = vb1.z; Bs[buf][kq1 + 3][r1] = vb1.w;
    };

    u64t acc[8][4];
#pragma unroll
    for (int i = 0; i < 8; i++)
#pragma unroll
        for (int j = 0; j < 4; j++) acc[i][j] = 0ull;

    LOAD(0); STORE(0);
    __syncthreads();

    int nk = K / BK;
    for (int kt = 0; kt < nk; kt++) {
        int cur = kt & 1;
        if (kt + 1 < nk) LOAD((kt + 1) * BK);

#pragma unroll
        for (int kk = 0; kk < BK; kk++) {
            float4 a0 = *(const float4*)&As[cur][kk][m0];
            float4 a1 = *(const float4*)&As[cur][kk][m0 + 4];
            const u64t* bp = (const u64t*)&Bs[cur][kk][n0];
            u64t b0 = bp[0], b1 = bp[1], b2 = bp[2], b3 = bp[3];

            u64t as[8];
            as[0] = f2pack(a0.x, a0.x); as[1] = f2pack(a0.y, a0.y);
            as[2] = f2pack(a0.z, a0.z); as[3] = f2pack(a0.w, a0.w);
            as[4] = f2pack(a1.x, a1.x); as[5] = f2pack(a1.y, a1.y);
            as[6] = f2pack(a1.z, a1.z); as[7] = f2pack(a1.w, a1.w);
#pragma unroll
            for (int i = 0; i < 8; i++) {
                acc[i][0] = ffma2(as[i], b0, acc[i][0]);
                acc[i][1] = ffma2(as[i], b1, acc[i][1]);
                acc[i][2] = ffma2(as[i], b2, acc[i][2]);
                acc[i][3] = ffma2(as[i], b3, acc[i][3]);
            }
        }

        if (kt + 1 < nk) STORE(cur ^ 1);
        __syncthreads();
    }

#pragma unroll
    for (int i = 0; i < 8; i++) {
        int m = bm + m0 + i;
#pragma unroll
        for (int j = 0; j < 4; j++) {
            float c0, c1;
            f2unpack(acc[i][j], c0, c1);
            int n = bn + n0 + 2 * j;
            if (n < N) {
                float v0 = c0;
                if (resid) v0 += resid[(size_t)m * N + n];
                C[(size_t)m * N + n] = v0;
            }
            if (n + 1 < N) {
                float v1 = c1;
                if (resid) v1 += resid[(size_t)m * N + n + 1];
                C[(size_t)m * N + n + 1] = v1;
            }
        }
    }
}

// ---------------------------------------------------------------------------
// Delta-rule recurrence, WY-chunked, 4 WARPS PER CHAIN (column-split W).
// Thread (r, g): row r, columns [8g, 8g+8) of the 32x32 fast-weight matrix.
// Per 4-step chunk: partial dots -> smem -> 1 barrier -> redundant per-row
// delta/output chain in all warps (no 2nd barrier) -> local rank-4 update.
// part[] is double-buffered across chunks so one barrier per chunk suffices.
// ---------------------------------------------------------------------------
__global__ __launch_bounds__(128)
void rec_kernel(const float* __restrict__ state,
                float* __restrict__ out_fw, int write_fw)
{
    int chain = blockIdx.x;            // 0..127
    int b = chain >> 3, h = chain & 7;
    int tid = threadIdx.x;
    int r = tid & 31;                  // row
    int g = tid >> 5;                  // column group (warp id)

    u64t Wp[4];
    const u64t* st = (const u64t*)(state + ((size_t)chain * DH + r) * DH + g * 8);
#pragma unroll
    for (int j = 0; j < 4; j++) Wp[j] = st[j];

    __shared__ __align__(16) float sk[2][TC * DH];
    __shared__ __align__(16) float sq[2][TC * DH];
    __shared__ __align__(16) float sv[2][TC * DH];
    __shared__ __align__(16) float sb_[2][TC * 2];
    __shared__ __align__(16) float scr[2][(TC / 4) * 16];
    __shared__ float part[2][8][32][5];   // [pbuf][s(0-3:A,4-7:Q)][row][g] padded

    const float* kb  = g_kn + (size_t)chain * SLEN * DH;
    const float* qb  = g_qn + (size_t)chain * SLEN * DH;
    const float* vb  = g_vn + (size_t)chain * SLEN * DH;
    const float* sbp = g_sc + (size_t)chain * SLEN * 2;
    const float* crb = g_cross + (size_t)chain * NCHUNK * 16;

    auto REFILL = [&](int cc, int buf) {
        const float4* kp = (const float4*)(kb + (size_t)cc * TC * DH);
        const float4* qp = (const float4*)(qb + (size_t)cc * TC * DH);
        const float4* vp = (const float4*)(vb + (size_t)cc * TC * DH);
        ((float4*)sk[buf])[tid] = kp[tid];
        ((float4*)sq[buf])[tid] = qp[tid];
        ((float4*)sv[buf])[tid] = vp[tid];
        if (tid < TC * 2) sb_[buf][tid] = sbp[cc * TC * 2 + tid];
        if (tid < 64)     scr[buf][tid] = crb[cc * 64 + tid];
    };

    REFILL(0, 0);
    __syncthreads();

    const int NCC = SLEN / TC;
    for (int cc = 0; cc < NCC; cc++) {
        int buf = cc & 1;
        if (cc + 1 < NCC) REFILL(cc + 1, buf ^ 1);

#pragma unroll
        for (int q4 = 0; q4 < TC / 4; q4++) {
            int tb = q4 * 4;
            int pc = (cc * (TC / 4) + q4) & 1;

            // per-thread 8-wide slices of k_s (kept for the update)
            u64t ks[4][4];
#pragma unroll
            for (int s = 0; s < 4; s++) {
                const u64t* kp = (const u64t*)&sk[buf][(tb + s) * DH + g * 8];
#pragma unroll
                for (int j = 0; j < 4; j++) ks[s][j] = kp[j];
            }

            // partial dots vs this thread's W slice
#pragma unroll
            for (int s = 0; s < 4; s++) {
                const u64t* qp = (const u64t*)&sq[buf][(tb + s) * DH + g * 8];
                part[pc][s][r][g]     = dot8(Wp, ks[s]);
                part[pc][s + 4][r][g] = dot8(Wp, qp);
            }
            __syncthreads();

            // redundant per-row reduction + WY chain (all 4 warps)
            float A0 = part[pc][0][r][0] + part[pc][0][r][1] + part[pc][0][r][2] + part[pc][0][r][3];
            float A1 = part[pc][1][r][0] + part[pc][1][r][1] + part[pc][1][r][2] + part[pc][1][r][3];
            float A2 = part[pc][2][r][0] + part[pc][2][r][1] + part[pc][2][r][2] + part[pc][2][r][3];
            float A3 = part[pc][3][r][0] + part[pc][3][r][1] + part[pc][3][r][2] + part[pc][3][r][3];
            float Q0 = part[pc][4][r][0] + part[pc][4][r][1] + part[pc][4][r][2] + part[pc][4][r][3];
            float Q1 = part[pc][5][r][0] + part[pc][5][r][1] + part[pc][5][r][2] + part[pc][5][r][3];
            float Q2 = part[pc][6][r][0] + part[pc][6][r][1] + part[pc][6][r][2] + part[pc][6][r][3];
            float Q3 = part[pc][7][r][0] + part[pc][7][r][1] + part[pc][7][r][2] + part[pc][7][r][3];

            float be0 = sb_[buf][(tb + 0) * 2], be1 = sb_[buf][(tb + 1) * 2];
            float be2 = sb_[buf][(tb + 2) * 2], be3 = sb_[buf][(tb + 3) * 2];
            float vv0 = sv[buf][(tb + 0) * DH + r];
            float vv1 = sv[buf][(tb + 1) * DH + r];
            float vv2 = sv[buf][(tb + 2) * DH + r];
            float vv3 = sv[buf][(tb + 3) * DH + r];
            const float* cr = &scr[buf][q4 * 16];

            float d0 = fmaf(-be0, A0, be0 * vv0);
            float p1 = fmaf(-be1, A1, be1 * vv1);
            float p2 = fmaf(-be2, A2, be2 * vv2);
            float p3 = fmaf(-be3, A3, be3 * vv3);
            float d1 = fmaf(d0, cr[10], p1);
            float d2 = fmaf(d1, cr[13], fmaf(d0, cr[11], p2));
            float d3 = fmaf(d2, cr[15], fmaf(d1, cr[14], fmaf(d0, cr[12], p3)));

            // outputs: warp g stores o_g (one STG per thread per chunk)
            float og;
            if (g == 0)      og = fmaf(d0, cr[0], Q0);
            else if (g == 1) og = fmaf(d1, cr[4], fmaf(d0, cr[1], Q1));
            else if (g == 2) og = fmaf(d2, cr[7], fmaf(d1, cr[5], fmaf(d0, cr[2], Q2)));
            else             og = fmaf(d3, cr[9], fmaf(d2, cr[8], fmaf(d1, cr[6], fmaf(d0, cr[3], Q3))));

            int t = cc * TC + tb + g;
            g_oseq[((size_t)t * BSZ + b) * IND + h * DH + r] = og;

            // local rank-4 update on this thread's 8-column slice
            u64t D0 = f2pack(d0, d0), D1 = f2pack(d1, d1);
            u64t D2 = f2pack(d2, d2), D3 = f2pack(d3, d3);
#pragma unroll
            for (int j = 0; j < 4; j++) {
                u64t w = Wp[j];
                w = ffma2(D0, ks[0][j], w);
                w = ffma2(D1, ks[1][j], w);
                w = ffma2(D2, ks[2][j], w);
                w = ffma2(D3, ks[3][j], w);
                Wp[j] = w;
            }
        }
    }

    if (write_fw) {
        u64t* fw = (u64t*)(out_fw + ((size_t)chain * DH + r) * DH + g * 8);
#pragma unroll
        for (int j = 0; j < 4; j++) fw[j] = Wp[j];
    }
}

// ---------------------------------------------------------------------------
extern "C" void kernel_launch(void* const* d_in, const int* in_sizes, int n_in,
                              void* d_out, int out_size)
{
    const float* x        = (const float*)d_in[0];
    const float* state    = (const float*)d_in[1];
    const float* W_slow   = (const float*)d_in[2];
    const float* ln_gamma = (const float*)d_in[3];
    const float* ln_beta  = (const float*)d_in[4];
    const float* W_out    = (const float*)d_in[5];
    float* out = (float*)d_out;

    float* normed; cudaGetSymbolAddress((void**)&normed, g_normed);
    float* qkvb;   cudaGetSymbolAddress((void**)&qkvb,   g_qkvb);
    float* oseq;   cudaGetSymbolAddress((void**)&oseq,   g_oseq);

    // 1) LayerNorm
    ln_kernel<<<NTOK, IND>>>(x, ln_gamma, ln_beta);

    // 2) qkvb = normed @ W_slow^T   [16384 x 776]
    dim3 gB(NTOK / BM, (PROJ + BN - 1) / BN);
    gemm_nt<<<gB, 256>>>(normed, W_slow, qkvb, NTOK, PROJ, IND, nullptr);

    // 3) prep: activations + normalizers + beta + k.q, chain-major
    prep_kernel<<<SLEN * NCHAIN / 8, 256>>>();

    // 3b) prep2: WY cross terms per 4-step chunk
    prep2_kernel<<<NCHAIN * NCHUNK / 8, 256>>>();

    // 4) delta-rule recurrence (WY-chunked, 4 warps/chain)
    int write_fw = (out_size >= (int)((size_t)NTOK * IND + FW_ELEMS)) ? 1 : 0;
    rec_kernel<<<NCHAIN, 128>>>(state, out + (size_t)NTOK * IND, write_fw);

    // 5) out = x + oseq @ W_out^T   [16384 x 256]
    dim3 gD(NTOK / BM, (IND + BN - 1) / BN);
    gemm_nt<<<gD, 256>>>(oseq, W_out, out, NTOK, IND, IND, x);
}

// round 8
// speedup vs baseline: 2.2293x; 1.4266x over previous
#include <cuda_runtime.h>
#include <cstdint>

#define SLEN 1024
#define BSZ  16
#define IND  256
#define NH   8
#define DH   32
#define PROJ 776              // NH*(3*DH+1)
#define NTOK (SLEN*BSZ)       // 16384
#define NCHAIN (BSZ*NH)       // 128
#define FW_ELEMS (NCHAIN*DH*DH)
#define TC   16               // time steps staged per smem refill
#define NCHUNK (SLEN/4)       // 4-step WY chunks per chain

// Scratch (static device globals; no runtime allocation)
__device__ float g_normed[(size_t)NTOK*IND];
__device__ float g_qkvb[(size_t)NTOK*PROJ];
__device__ float g_oseq[(size_t)NTOK*IND];
// chain-major prepped streams: [chain][t][lane]
__device__ float g_kn[(size_t)NCHAIN*SLEN*DH];
__device__ float g_qn[(size_t)NCHAIN*SLEN*DH];
__device__ float g_vn[(size_t)NCHAIN*SLEN*DH];
__device__ float g_sc[(size_t)NCHAIN*SLEN*2];        // (beta, -) per step
// WY cross terms per 4-step chunk: [chain][chunk][16]
__device__ float g_cross[(size_t)NCHAIN*NCHUNK*16];

// ---------------------------------------------------------------------------
// Packed f32x2 helpers (Blackwell)
// ---------------------------------------------------------------------------
typedef unsigned long long u64t;

__device__ __forceinline__ u64t f2pack(float lo, float hi) {
    u64t r;
    asm("mov.b64 %0, {%1, %2};" : "=l"(r) : "f"(lo), "f"(hi));
    return r;
}
__device__ __forceinline__ void f2unpack(u64t v, float& lo, float& hi) {
    asm("mov.b64 {%0, %1}, %2;" : "=f"(lo), "=f"(hi) : "l"(v));
}
__device__ __forceinline__ u64t ffma2(u64t a, u64t b, u64t c) {
    u64t d;
    asm("fma.rn.f32x2 %0, %1, %2, %3;" : "=l"(d) : "l"(a), "l"(b), "l"(c));
    return d;
}
__device__ __forceinline__ uint32_t to_tf32(float x) {
    uint32_t u;
    asm("cvt.rna.tf32.f32 %0, %1;" : "=r"(u) : "f"(x));
    return u;
}

// 8-wide dot of packed slices (4 x f32x2)
__device__ __forceinline__ float dot8(const u64t* __restrict__ Wp,
                                      const u64t* __restrict__ vp) {
    u64t a = 0ull, b = 0ull;
    a = ffma2(Wp[0], vp[0], a); b = ffma2(Wp[1], vp[1], b);
    a = ffma2(Wp[2], vp[2], a); b = ffma2(Wp[3], vp[3], b);
    float x0, x1, y0, y1;
    f2unpack(a, x0, x1); f2unpack(b, y0, y1);
    return (x0 + y0) + (x1 + y1);
}

// ---------------------------------------------------------------------------
__global__ void noop_kernel() {}

// ---------------------------------------------------------------------------
// LayerNorm: one block (256 threads) per token row
// ---------------------------------------------------------------------------
__global__ void ln_kernel(const float* __restrict__ x,
                          const float* __restrict__ gamma,
                          const float* __restrict__ beta)
{
    int row = blockIdx.x;
    int tid = threadIdx.x;
    float v = x[(size_t)row * IND + tid];
    float s = v, s2 = v * v;
#pragma unroll
    for (int o = 16; o > 0; o >>= 1) {
        s  += __shfl_xor_sync(0xffffffffu, s,  o);
        s2 += __shfl_xor_sync(0xffffffffu, s2, o);
    }
    __shared__ float sh[2][8];
    int w = tid >> 5, l = tid & 31;
    if (l == 0) { sh[0][w] = s; sh[1][w] = s2; }
    __syncthreads();
    float ts = 0.f, ts2 = 0.f;
#pragma unroll
    for (int i = 0; i < 8; i++) { ts += sh[0][i]; ts2 += sh[1][i]; }
    float mu  = ts * (1.0f / IND);
    float var = ts2 * (1.0f / IND) - mu * mu;
    float r   = rsqrtf(var + 1e-5f);
    g_normed[(size_t)row * IND + tid] = (v - mu) * r * gamma[tid] + beta[tid];
}

// ---------------------------------------------------------------------------
// TF32 tensor-core GEMM: C[M,N] = A[M,K] * B[N,K]^T
// Block 128x128, BK=16, 8 warps (4x2), warp tile 32x64, mma.m16n8k8.tf32
// ---------------------------------------------------------------------------
#define TBM 128
#define TBN 128
#define TBK 16
#define TPAD 20   // smem row stride (floats); fragment loads hit 32 distinct banks

__global__ __launch_bounds__(256)
void gemm_tf32(const float* __restrict__ A, const float* __restrict__ B,
               float* __restrict__ C, int M, int N, int K)
{
    __shared__ uint32_t As[2][TBM][TPAD];   // [m][k] tf32 bits
    __shared__ uint32_t Bs[2][TBN][TPAD];   // [n][k] tf32 bits

    int bm = blockIdx.x * TBM;
    int bn = blockIdx.y * TBN;
    int tid = threadIdx.x;
    int wid = tid >> 5, lane = tid & 31;
    int warpM = wid & 3, warpN = wid >> 2;        // 4 x 2 warp grid
    int gID = lane >> 2, tIG = lane & 3;
    int wm0 = warpM * 32, wn0 = warpN * 64;

    // global->reg staging: per buffer each thread loads 2 float4 from A, 2 from B
    int f0 = tid,       r0 = f0 >> 2, kc0 = (f0 & 3) * 4;
    int f1 = tid + 256, r1 = f1 >> 2, kc1 = (f1 & 3) * 4;

    float4 va0, va1, vb0, vb1;
    auto LOAD = [&](int k0) {
        va0 = *(const float4*)(A + (size_t)(bm + r0) * K + k0 + kc0);
        va1 = *(const float4*)(A + (size_t)(bm + r1) * K + k0 + kc1);
        vb0 = make_float4(0.f, 0.f, 0.f, 0.f);
        vb1 = make_float4(0.f, 0.f, 0.f, 0.f);
        if (bn + r0 < N) vb0 = *(const float4*)(B + (size_t)(bn + r0) * K + k0 + kc0);
        if (bn + r1 < N) vb1 = *(const float4*)(B + (size_t)(bn + r1) * K + k0 + kc1);
    };
    auto STORE = [&](int buf) {
        As[buf][r0][kc0 + 0] = to_tf32(va0.x); As[buf][r0][kc0 + 1] = to_tf32(va0.y);
        As[buf][r0][kc0 + 2] = to_tf32(va0.z); As[buf][r0][kc0 + 3] = to_tf32(va0.w);
        As[buf][r1][kc1 + 0] = to_tf32(va1.x); As[buf][r1][kc1 + 1] = to_tf32(va1.y);
        As[buf][r1][kc1 + 2] = to_tf32(va1.z); As[buf][r1][kc1 + 3] = to_tf32(va1.w);
        Bs[buf][r0][kc0 + 0] = to_tf32(vb0.x); Bs[buf][r0][kc0 + 1] = to_tf32(vb0.y);
        Bs[buf][r0][kc0 + 2] = to_tf32(vb0.z); Bs[buf][r0][kc0 + 3] = to_tf32(vb0.w);
        Bs[buf][r1][kc1 + 0] = to_tf32(vb1.x); Bs[buf][r1][kc1 + 1] = to_tf32(vb1.y);
        Bs[buf][r1][kc1 + 2] = to_tf32(vb1.z); Bs[buf][r1][kc1 + 3] = to_tf32(vb1.w);
    };

    float acc[2][8][4];
#pragma unroll
    for (int i = 0; i < 2; i++)
#pragma unroll
        for (int j = 0; j < 8; j++)
#pragma unroll
            for (int c = 0; c < 4; c++) acc[i][j][c] = 0.f;

    LOAD(0); STORE(0);
    __syncthreads();

    int nk = K / TBK;
    for (int kt = 0; kt < nk; kt++) {
        int cur = kt & 1;
        if (kt + 1 < nk) LOAD((kt + 1) * TBK);

#pragma unroll
        for (int k8 = 0; k8 < TBK; k8 += 8) {
            uint32_t af[2][4];
#pragma unroll
            for (int mf = 0; mf < 2; mf++) {
                int row = wm0 + mf * 16 + gID;
                af[mf][0] = As[cur][row][k8 + tIG];
                af[mf][1] = As[cur][row + 8][k8 + tIG];
                af[mf][2] = As[cur][row][k8 + tIG + 4];
                af[mf][3] = As[cur][row + 8][k8 + tIG + 4];
            }
#pragma unroll
            for (int nf = 0; nf < 8; nf++) {
                int col = wn0 + nf * 8 + gID;
                uint32_t b0 = Bs[cur][col][k8 + tIG];
                uint32_t b1 = Bs[cur][col][k8 + tIG + 4];
#pragma unroll
                for (int mf = 0; mf < 2; mf++) {
                    asm volatile(
                        "mma.sync.aligned.m16n8k8.row.col.f32.tf32.tf32.f32 "
                        "{%0,%1,%2,%3}, {%4,%5,%6,%7}, {%8,%9}, {%0,%1,%2,%3};"
                        : "+f"(acc[mf][nf][0]), "+f"(acc[mf][nf][1]),
                          "+f"(acc[mf][nf][2]), "+f"(acc[mf][nf][3])
                        : "r"(af[mf][0]), "r"(af[mf][1]), "r"(af[mf][2]), "r"(af[mf][3]),
                          "r"(b0), "r"(b1));
                }
            }
        }

        if (kt + 1 < nk) STORE(cur ^ 1);
        __syncthreads();
    }

    // epilogue: c0,c1 = row gID cols 2t,2t+1 ; c2,c3 = row gID+8
#pragma unroll
    for (int mf = 0; mf < 2; mf++) {
#pragma unroll
        for (int nf = 0; nf < 8; nf++) {
            int m = bm + wm0 + mf * 16 + gID;
            int n = bn + wn0 + nf * 8 + 2 * tIG;
            if (n < N) {
                *(float2*)(C + (size_t)m * N + n) =
                    make_float2(acc[mf][nf][0], acc[mf][nf][1]);
                *(float2*)(C + (size_t)(m + 8) * N + n) =
                    make_float2(acc[mf][nf][2], acc[mf][nf][3]);
            }
        }
    }
}

// ---------------------------------------------------------------------------
// Fused prep: one warp per (chain, 4-step chunk). Computes elu+1, the 8 sum
// normalizers, sigmoid(beta), AND all 16 WY cross terms directly from regs.
// ---------------------------------------------------------------------------
__global__ __launch_bounds__(256)
void prep_fused()
{
    int gw   = blockIdx.x * 8 + (threadIdx.x >> 5);   // 0 .. NCHAIN*NCHUNK-1
    int lane = threadIdx.x & 31;
    int ch   = gw >> 8;          // chain
    int cu   = gw & 255;         // chunk
    int t0   = cu * 4;
    int b    = ch >> 3, h = ch & 7;

    float eq[4], ek[4], vv[4], bta[4];
#pragma unroll
    for (int s = 0; s < 4; s++) {
        const float* base = g_qkvb + ((size_t)(t0 + s) * BSZ + b) * PROJ + h * 97;
        float q = base[lane], k = base[32 + lane];
        vv[s]  = base[64 + lane];
        bta[s] = base[96];
        eq[s] = q > 0.f ? q + 1.f : __expf(q);
        ek[s] = k > 0.f ? k + 1.f : __expf(k);
    }

    // 24 raw sums in one butterfly pass
    float r[24];
#pragma unroll
    for (int s = 0; s < 4; s++) { r[s] = eq[s]; r[4 + s] = ek[s]; }
    r[8]  = ek[0] * eq[0]; r[9]  = ek[0] * eq[1]; r[10] = ek[0] * eq[2]; r[11] = ek[0] * eq[3];
    r[12] = ek[1] * eq[1]; r[13] = ek[1] * eq[2]; r[14] = ek[1] * eq[3];
    r[15] = ek[2] * eq[2]; r[16] = ek[2] * eq[3]; r[17] = ek[3] * eq[3];
    r[18] = ek[0] * ek[1]; r[19] = ek[0] * ek[2]; r[20] = ek[0] * ek[3];
    r[21] = ek[1] * ek[2]; r[22] = ek[1] * ek[3]; r[23] = ek[2] * ek[3];
#pragma unroll
    for (int o = 16; o > 0; o >>= 1) {
#pragma unroll
        for (int i = 0; i < 24; i++)
            r[i] += __shfl_xor_sync(0xffffffffu, r[i], o);
    }

    float rsq[4], rsk[4];
#pragma unroll
    for (int s = 0; s < 4; s++) {
        rsq[s] = 1.0f / (r[s] + 1e-5f);
        rsk[s] = 1.0f / (r[4 + s] + 1e-5f);
    }

    // normalized streams (chain-major)
#pragma unroll
    for (int s = 0; s < 4; s++) {
        size_t oi = ((size_t)ch * SLEN + t0 + s) * DH + lane;
        g_qn[oi] = eq[s] * rsq[s];
        g_kn[oi] = ek[s] * rsk[s];
        g_vn[oi] = vv[s];
    }

    if (lane == 0) {
        float be[4];
#pragma unroll
        for (int s = 0; s < 4; s++) {
            be[s] = 1.0f / (1.0f + __expf(-bta[s]));
            g_sc[((size_t)ch * SLEN + t0 + s) * 2] = be[s];
        }
        // cross terms: kq_ij = rawKQ * rsk_i * rsq_j ; kk_ij = -be_j * raw * rsk_i * rsk_j
        float c0  = r[8]  * rsk[0] * rsq[0];
        float c1  = r[9]  * rsk[0] * rsq[1];
        float c2  = r[10] * rsk[0] * rsq[2];
        float c3  = r[11] * rsk[0] * rsq[3];
        float c4  = r[12] * rsk[1] * rsq[1];
        float c5  = r[13] * rsk[1] * rsq[2];
        float c6  = r[14] * rsk[1] * rsq[3];
        float c7  = r[15] * rsk[2] * rsq[2];
        float c8  = r[16] * rsk[2] * rsq[3];
        float c9  = r[17] * rsk[3] * rsq[3];
        float c10 = -be[1] * r[18] * rsk[0] * rsk[1];
        float c11 = -be[2] * r[19] * rsk[0] * rsk[2];
        float c12 = -be[3] * r[20] * rsk[0] * rsk[3];
        float c13 = -be[2] * r[21] * rsk[1] * rsk[2];
        float c14 = -be[3] * r[22] * rsk[1] * rsk[3];
        float c15 = -be[3] * r[23] * rsk[2] * rsk[3];
        float4* o = (float4*)(g_cross + ((size_t)ch * NCHUNK + cu) * 16);
        o[0] = make_float4(c0,  c1,  c2,  c3);
        o[1] = make_float4(c4,  c5,  c6,  c7);
        o[2] = make_float4(c8,  c9,  c10, c11);
        o[3] = make_float4(c12, c13, c14, c15);
    }
}

// ---------------------------------------------------------------------------
// Tiled NT GEMM (fp32 f32x2) — used for gemm2 (keeps the residual in fp32)
// ---------------------------------------------------------------------------
#define BM 128
#define BN 128
#define BK 16
#define LDS_PAD 132

__global__ __launch_bounds__(256)
void gemm_nt(const float* __restrict__ A, const float* __restrict__ B,
             float* __restrict__ C, int M, int N, int K,
             const float* __restrict__ resid)
{
    __shared__ __align__(16) float As[2][BK][LDS_PAD];
    __shared__ __align__(16) float Bs[2][BK][LDS_PAD];

    int bm = blockIdx.x * BM;
    int bn = blockIdx.y * BN;
    int tid = threadIdx.x;
    int tx = tid & 15, ty = tid >> 4;
    int m0 = ty * 8, n0 = tx * 8;

    int f0 = tid,       r0 = f0 >> 2, kq0 = (f0 & 3) * 4;
    int f1 = tid + 256, r1 = f1 >> 2, kq1 = (f1 & 3) * 4;

    float4 va0, va1, vb0, vb1;

    auto LOAD = [&](int k0) {
        va0 = *(const float4*)(A + (size_t)(bm + r0) * K + k0 + kq0);
        va1 = *(const float4*)(A + (size_t)(bm + r1) * K + k0 + kq1);
        vb0 = make_float4(0.f, 0.f, 0.f, 0.f);
        vb1 = make_float4(0.f, 0.f, 0.f, 0.f);
        if (bn + r0 < N) vb0 = *(const float4*)(B + (size_t)(bn + r0) * K + k0 + kq0);
        if (bn + r1 < N) vb1 = *(const float4*)(B + (size_t)(bn + r1) * K + k0 + kq1);
    };
    auto STORE = [&](int buf) {
        As[buf][kq0 + 0][r0] = va0.x; As[buf][kq0 + 1][r0] = va0.y;
        As[buf][kq0 + 2][r0] = va0.z; As[buf][kq0 + 3][r0] = va0.w;
        As[buf][kq1 + 0][r1] = va1.x; As[buf][kq1 + 1][r1] = va1.y;
        As[buf][kq1 + 2][r1] = va1.z; As[buf][kq1 + 3][r1] = va1.w;
        Bs[buf][kq0 + 0][r0] = vb0.x; Bs[buf][kq0 + 1][r0] = vb0.y;
        Bs[buf][kq0 + 2][r0] = vb0.z; Bs[buf][kq0 + 3][r0] = vb0.w;
        Bs[buf][kq1 + 0][r1] = vb1.x; Bs[buf][kq1 + 1][r1] = vb1.y;
        Bs[buf][kq1 + 2][r1] = vb1.z; Bs[buf][kq1 + 3][r1] = vb1.w;
    };

    u64t acc[8][4];
#pragma unroll
    for (int i = 0; i < 8; i++)
#pragma unroll
        for (int j = 0; j < 4; j++) acc[i][j] = 0ull;

    LOAD(0); STORE(0);
    __syncthreads();

    int nk = K / BK;
    for (int kt = 0; kt < nk; kt++) {
        int cur = kt & 1;
        if (kt + 1 < nk) LOAD((kt + 1) * BK);

#pragma unroll
        for (int kk = 0; kk < BK; kk++) {
            float4 a0 = *(const float4*)&As[cur][kk][m0];
            float4 a1 = *(const float4*)&As[cur][kk][m0 + 4];
            const u64t* bp = (const u64t*)&Bs[cur][kk][n0];
            u64t b0 = bp[0], b1 = bp[1], b2 = bp[2], b3 = bp[3];

            u64t as[8];
            as[0] = f2pack(a0.x, a0.x); as[1] = f2pack(a0.y, a0.y);
            as[2] = f2pack(a0.z, a0.z); as[3] = f2pack(a0.w, a0.w);
            as[4] = f2pack(a1.x, a1.x); as[5] = f2pack(a1.y, a1.y);
            as[6] = f2pack(a1.z, a1.z); as[7] = f2pack(a1.w, a1.w);
#pragma unroll
            for (int i = 0; i < 8; i++) {
                acc[i][0] = ffma2(as[i], b0, acc[i][0]);
                acc[i][1] = ffma2(as[i], b1, acc[i][1]);
                acc[i][2] = ffma2(as[i], b2, acc[i][2]);
                acc[i][3] = ffma2(as[i], b3, acc[i][3]);
            }
        }

        if (kt + 1 < nk) STORE(cur ^ 1);
        __syncthreads();
    }

#pragma unroll
    for (int i = 0; i < 8; i++) {
        int m = bm + m0 + i;
#pragma unroll
        for (int j = 0; j < 4; j++) {
            float c0, c1;
            f2unpack(acc[i][j], c0, c1);
            int n = bn + n0 + 2 * j;
            if (n < N) {
                float v0 = c0;
                if (resid) v0 += resid[(size_t)m * N + n];
                C[(size_t)m * N + n] = v0;
            }
            if (n + 1 < N) {
                float v1 = c1;
                if (resid) v1 += resid[(size_t)m * N + n + 1];
                C[(size_t)m * N + n + 1] = v1;
            }
        }
    }
}

// ---------------------------------------------------------------------------
// Delta-rule recurrence, WY-chunked, 4 warps per chain (column-split W)
// ---------------------------------------------------------------------------
__global__ __launch_bounds__(128)
void rec_kernel(const float* __restrict__ state,
                float* __restrict__ out_fw, int write_fw)
{
    int chain = blockIdx.x;            // 0..127
    int b = chain >> 3, h = chain & 7;
    int tid = threadIdx.x;
    int r = tid & 31;                  // row
    int g = tid >> 5;                  // column group (warp id)

    u64t Wp[4];
    const u64t* st = (const u64t*)(state + ((size_t)chain * DH + r) * DH + g * 8);
#pragma unroll
    for (int j = 0; j < 4; j++) Wp[j] = st[j];

    __shared__ __align__(16) float sk[2][TC * DH];
    __shared__ __align__(16) float sq[2][TC * DH];
    __shared__ __align__(16) float sv[2][TC * DH];
    __shared__ __align__(16) float sb_[2][TC * 2];
    __shared__ __align__(16) float scr[2][(TC / 4) * 16];
    __shared__ float part[2][8][32][5];   // [pbuf][s(0-3:A,4-7:Q)][row][g] padded

    const float* kb  = g_kn + (size_t)chain * SLEN * DH;
    const float* qb  = g_qn + (size_t)chain * SLEN * DH;
    const float* vb  = g_vn + (size_t)chain * SLEN * DH;
    const float* sbp = g_sc + (size_t)chain * SLEN * 2;
    const float* crb = g_cross + (size_t)chain * NCHUNK * 16;

    auto REFILL = [&](int cc, int buf) {
        const float4* kp = (const float4*)(kb + (size_t)cc * TC * DH);
        const float4* qp = (const float4*)(qb + (size_t)cc * TC * DH);
        const float4* vp = (const float4*)(vb + (size_t)cc * TC * DH);
        ((float4*)sk[buf])[tid] = kp[tid];
        ((float4*)sq[buf])[tid] = qp[tid];
        ((float4*)sv[buf])[tid] = vp[tid];
        if (tid < TC * 2) sb_[buf][tid] = sbp[cc * TC * 2 + tid];
        if (tid < 64)     scr[buf][tid] = crb[cc * 64 + tid];
    };

    REFILL(0, 0);
    __syncthreads();

    const int NCC = SLEN / TC;
    for (int cc = 0; cc < NCC; cc++) {
        int buf = cc & 1;
        if (cc + 1 < NCC) REFILL(cc + 1, buf ^ 1);

#pragma unroll
        for (int q4 = 0; q4 < TC / 4; q4++) {
            int tb = q4 * 4;
            int pc = (cc * (TC / 4) + q4) & 1;

            u64t ks[4][4];
#pragma unroll
            for (int s = 0; s < 4; s++) {
                const u64t* kp = (const u64t*)&sk[buf][(tb + s) * DH + g * 8];
#pragma unroll
                for (int j = 0; j < 4; j++) ks[s][j] = kp[j];
            }

#pragma unroll
            for (int s = 0; s < 4; s++) {
                const u64t* qp = (const u64t*)&sq[buf][(tb + s) * DH + g * 8];
                part[pc][s][r][g]     = dot8(Wp, ks[s]);
                part[pc][s + 4][r][g] = dot8(Wp, qp);
            }
            __syncthreads();

            float A0 = part[pc][0][r][0] + part[pc][0][r][1] + part[pc][0][r][2] + part[pc][0][r][3];
            float A1 = part[pc][1][r][0] + part[pc][1][r][1] + part[pc][1][r][2] + part[pc][1][r][3];
            float A2 = part[pc][2][r][0] + part[pc][2][r][1] + part[pc][2][r][2] + part[pc][2][r][3];
            float A3 = part[pc][3][r][0] + part[pc][3][r][1] + part[pc][3][r][2] + part[pc][3][r][3];
            float Q0 = part[pc][4][r][0] + part[pc][4][r][1] + part[pc][4][r][2] + part[pc][4][r][3];
            float Q1 = part[pc][5][r][0] + part[pc][5][r][1] + part[pc][5][r][2] + part[pc][5][r][3];
            float Q2 = part[pc][6][r][0] + part[pc][6][r][1] + part[pc][6][r][2] + part[pc][6][r][3];
            float Q3 = part[pc][7][r][0] + part[pc][7][r][1] + part[pc][7][r][2] + part[pc][7][r][3];

            float be0 = sb_[buf][(tb + 0) * 2], be1 = sb_[buf][(tb + 1) * 2];
            float be2 = sb_[buf][(tb + 2) * 2], be3 = sb_[buf][(tb + 3) * 2];
            float vv0 = sv[buf][(tb + 0) * DH + r];
            float vv1 = sv[buf][(tb + 1) * DH + r];
            float vv2 = sv[buf][(tb + 2) * DH + r];
            float vv3 = sv[buf][(tb + 3) * DH + r];
            const float* cr = &scr[buf][q4 * 16];

            float d0 = fmaf(-be0, A0, be0 * vv0);
            float p1 = fmaf(-be1, A1, be1 * vv1);
            float p2 = fmaf(-be2, A2, be2 * vv2);
            float p3 = fmaf(-be3, A3, be3 * vv3);
            float d1 = fmaf(d0, cr[10], p1);
            float d2 = fmaf(d1, cr[13], fmaf(d0, cr[11], p2));
            float d3 = fmaf(d2, cr[15], fmaf(d1, cr[14], fmaf(d0, cr[12], p3)));

            float og;
            if (g == 0)      og = fmaf(d0, cr[0], Q0);
            else if (g == 1) og = fmaf(d1, cr[4], fmaf(d0, cr[1], Q1));
            else if (g == 2) og = fmaf(d2, cr[7], fmaf(d1, cr[5], fmaf(d0, cr[2], Q2)));
            else             og = fmaf(d3, cr[9], fmaf(d2, cr[8], fmaf(d1, cr[6], fmaf(d0, cr[3], Q3))));

            int t = cc * TC + tb + g;
            g_oseq[((size_t)t * BSZ + b) * IND + h * DH + r] = og;

            u64t D0 = f2pack(d0, d0), D1 = f2pack(d1, d1);
            u64t D2 = f2pack(d2, d2), D3 = f2pack(d3, d3);
#pragma unroll
            for (int j = 0; j < 4; j++) {
                u64t w = Wp[j];
                w = ffma2(D0, ks[0][j], w);
                w = ffma2(D1, ks[1][j], w);
                w = ffma2(D2, ks[2][j], w);
                w = ffma2(D3, ks[3][j], w);
                Wp[j] = w;
            }
        }
    }

    if (write_fw) {
        u64t* fw = (u64t*)(out_fw + ((size_t)chain * DH + r) * DH + g * 8);
#pragma unroll
        for (int j = 0; j < 4; j++) fw[j] = Wp[j];
    }
}

// ---------------------------------------------------------------------------
extern "C" void kernel_launch(void* const* d_in, const int* in_sizes, int n_in,
                              void* d_out, int out_size)
{
    const float* x        = (const float*)d_in[0];
    const float* state    = (const float*)d_in[1];
    const float* W_slow   = (const float*)d_in[2];
    const float* ln_gamma = (const float*)d_in[3];
    const float* ln_beta  = (const float*)d_in[4];
    const float* W_out    = (const float*)d_in[5];
    float* out = (float*)d_out;

    float* normed; cudaGetSymbolAddress((void**)&normed, g_normed);
    float* qkvb;   cudaGetSymbolAddress((void**)&qkvb,   g_qkvb);
    float* oseq;   cudaGetSymbolAddress((void**)&oseq,   g_oseq);

    // instrumentation: shift ncu capture (launch idx 3) onto gemm_tf32
    noop_kernel<<<1, 32>>>();
    noop_kernel<<<1, 32>>>();

    // 1) LayerNorm
    ln_kernel<<<NTOK, IND>>>(x, ln_gamma, ln_beta);

    // 2) qkvb = normed @ W_slow^T   [16384 x 776]  — tf32 tensor cores
    dim3 gB(NTOK / TBM, (PROJ + TBN - 1) / TBN);
    gemm_tf32<<<gB, 256>>>(normed, W_slow, qkvb, NTOK, PROJ, IND);

    // 3) fused prep: activations + normalizers + beta + WY cross terms
    prep_fused<<<NCHAIN * NCHUNK / 8, 256>>>();

    // 4) delta-rule recurrence (WY-chunked, 4 warps/chain)
    int write_fw = (out_size >= (int)((size_t)NTOK * IND + FW_ELEMS)) ? 1 : 0;
    rec_kernel<<<NCHAIN, 128>>>(state, out + (size_t)NTOK * IND, write_fw);

    // 5) out = x + oseq @ W_out^T   [16384 x 256]  — fp32 (residual path)
    dim3 gD(NTOK / BM, (IND + BN - 1) / BN);
    gemm_nt<<<gD, 256>>>(oseq, W_out, out, NTOK, IND, IND, x);
}

// round 9
// speedup vs baseline: 2.5413x; 1.1399x over previous
#include <cuda_runtime.h>
#include <cstdint>

#define SLEN 1024
#define BSZ  16
#define IND  256
#define NH   8
#define DH   32
#define PROJ 776              // NH*(3*DH+1)
#define NTOK (SLEN*BSZ)       // 16384
#define NCHAIN (BSZ*NH)       // 128
#define FW_ELEMS (NCHAIN*DH*DH)
#define TCH  16               // staged steps per refill (2 chunks of 8)
#define CH8  8                // WY chunk size
#define NCH8 (SLEN/CH8)       // 128 chunks per chain
#define RTOT (PROJ*IND + IND*IND)   // 264192 weight elems to round

// Scratch (static device globals; no runtime allocation)
__device__ __align__(16) float g_normed[(size_t)NTOK*IND];   // tf32-rounded
__device__ __align__(16) float g_qkvb[(size_t)NTOK*PROJ];
__device__ __align__(16) float g_oseq[(size_t)NTOK*IND];     // tf32-rounded
__device__ __align__(16) float g_kn[(size_t)NCHAIN*SLEN*DH];
__device__ __align__(16) float g_qn[(size_t)NCHAIN*SLEN*DH];
__device__ __align__(16) float g_vn[(size_t)NCHAIN*SLEN*DH];
__device__ __align__(16) float g_beta[(size_t)NCHAIN*SLEN];
__device__ __align__(16) float g_cross[(size_t)NCHAIN*NCH8*64];
__device__ __align__(16) float g_wslow_t[(size_t)PROJ*IND];  // tf32-rounded
__device__ __align__(16) float g_wout_t[(size_t)IND*IND];    // tf32-rounded

// ---------------------------------------------------------------------------
// helpers
// ---------------------------------------------------------------------------
typedef unsigned long long u64t;

__device__ __forceinline__ u64t f2pack(float lo, float hi) {
    u64t r; asm("mov.b64 %0, {%1, %2};" : "=l"(r) : "f"(lo), "f"(hi)); return r;
}
__device__ __forceinline__ void f2unpack(u64t v, float& lo, float& hi) {
    asm("mov.b64 {%0, %1}, %2;" : "=f"(lo), "=f"(hi) : "l"(v));
}
__device__ __forceinline__ u64t ffma2(u64t a, u64t b, u64t c) {
    u64t d; asm("fma.rn.f32x2 %0, %1, %2, %3;" : "=l"(d) : "l"(a), "l"(b), "l"(c)); return d;
}
__device__ __forceinline__ uint32_t to_tf32(float x) {
    uint32_t u; asm("cvt.rna.tf32.f32 %0, %1;" : "=r"(u) : "f"(x)); return u;
}
__device__ __forceinline__ float rnd_tf32(float x) {
    return __uint_as_float(to_tf32(x));
}
__device__ __forceinline__ uint32_t smem_u32(const void* p) {
    return (uint32_t)__cvta_generic_to_shared(p);
}
__device__ __forceinline__ void cp16(uint32_t d, const void* s, int ssz) {
    asm volatile("cp.async.ca.shared.global [%0], [%1], 16, %2;" :: "r"(d), "l"(s), "r"(ssz));
}
__device__ __forceinline__ void cp_commit() { asm volatile("cp.async.commit_group;" ::); }
__device__ __forceinline__ void cp_wait0()  { asm volatile("cp.async.wait_group 0;" ::); }

// 8-wide dot of packed slices (4 x f32x2)
__device__ __forceinline__ float dot8(const u64t* __restrict__ Wp,
                                      const u64t* __restrict__ vp) {
    u64t a = 0ull, b = 0ull;
    a = ffma2(Wp[0], vp[0], a); b = ffma2(Wp[1], vp[1], b);
    a = ffma2(Wp[2], vp[2], a); b = ffma2(Wp[3], vp[3], b);
    float x0, x1, y0, y1;
    f2unpack(a, x0, x1); f2unpack(b, y0, y1);
    return (x0 + y0) + (x1 + y1);
}

// upper-tri (i<=j) and strict (i<j) index maps over 8 steps
__host__ __device__ constexpr int UTx(int i, int j) { return i * (15 - i) / 2 + j; }
__host__ __device__ constexpr int STx(int i, int j) { return i * (13 - i) / 2 + j - 1; }

// ---------------------------------------------------------------------------
// Fused: LayerNorm (tf32-rounded output) + weight rounding
// blocks [0, NTOK): LN rows. blocks [NTOK, ...): round W_slow / W_out.
// ---------------------------------------------------------------------------
__global__ void ln_round_kernel(const float* __restrict__ x,
                                const float* __restrict__ gamma,
                                const float* __restrict__ beta,
                                const float* __restrict__ Wslow,
                                const float* __restrict__ Wout)
{
    int blk = blockIdx.x, tid = threadIdx.x;
    if (blk >= NTOK) {
        int i = (blk - NTOK) * 256 + tid;
        if (i < PROJ * IND)       g_wslow_t[i] = rnd_tf32(Wslow[i]);
        else if (i < RTOT)        g_wout_t[i - PROJ * IND] = rnd_tf32(Wout[i - PROJ * IND]);
        return;
    }
    float v = x[(size_t)blk * IND + tid];
    float s = v, s2 = v * v;
#pragma unroll
    for (int o = 16; o > 0; o >>= 1) {
        s  += __shfl_xor_sync(0xffffffffu, s,  o);
        s2 += __shfl_xor_sync(0xffffffffu, s2, o);
    }
    __shared__ float sh[2][8];
    int w = tid >> 5, l = tid & 31;
    if (l == 0) { sh[0][w] = s; sh[1][w] = s2; }
    __syncthreads();
    float ts = 0.f, ts2 = 0.f;
#pragma unroll
    for (int i = 0; i < 8; i++) { ts += sh[0][i]; ts2 += sh[1][i]; }
    float mu  = ts * (1.0f / IND);
    float var = ts2 * (1.0f / IND) - mu * mu;
    float rr  = rsqrtf(var + 1e-5f);
    g_normed[(size_t)blk * IND + tid] = rnd_tf32((v - mu) * rr * gamma[tid] + beta[tid]);
}

// ---------------------------------------------------------------------------
// TF32 tensor-core GEMM, cp.async streamed (operands pre-rounded to tf32):
// C[M,N] = A[M,K] * B[N,K]^T (+resid). Block 128x128, BK=16, 8 warps.
// ---------------------------------------------------------------------------
#define TBM 128
#define TBN 128
#define TBK 16
#define TPAD 20

__global__ __launch_bounds__(256)
void gemm_tf32(const float* __restrict__ A, const float* __restrict__ B,
               float* __restrict__ C, int M, int N, int K,
               const float* __restrict__ resid)
{
    __shared__ uint32_t As[2][TBM][TPAD];
    __shared__ uint32_t Bs[2][TBN][TPAD];

    int bm = blockIdx.x * TBM;
    int bn = blockIdx.y * TBN;
    int tid = threadIdx.x;
    int wid = tid >> 5, lane = tid & 31;
    int warpM = wid & 3, warpN = wid >> 2;
    int gID = lane >> 2, tIG = lane & 3;
    int wm0 = warpM * 32, wn0 = warpN * 64;

    int f0 = tid,       r0 = f0 >> 2, kc0 = (f0 & 3) * 4;
    int f1 = tid + 256, r1 = f1 >> 2, kc1 = (f1 & 3) * 4;

    uint32_t aA[2], aA1[2], aB[2], aB1[2];
#pragma unroll
    for (int bf = 0; bf < 2; bf++) {
        aA[bf]  = smem_u32(&As[bf][r0][kc0]);
        aA1[bf] = smem_u32(&As[bf][r1][kc1]);
        aB[bf]  = smem_u32(&Bs[bf][r0][kc0]);
        aB1[bf] = smem_u32(&Bs[bf][r1][kc1]);
    }
    int bz0 = (bn + r0 < N) ? 16 : 0;
    int bz1 = (bn + r1 < N) ? 16 : 0;

    auto LOADA = [&](int k0, int bf) {
        cp16(aA[bf],  A + (size_t)(bm + r0) * K + k0 + kc0, 16);
        cp16(aA1[bf], A + (size_t)(bm + r1) * K + k0 + kc1, 16);
        cp16(aB[bf],  B + (size_t)(bn + r0) * K + k0 + kc0, bz0);
        cp16(aB1[bf], B + (size_t)(bn + r1) * K + k0 + kc1, bz1);
        cp_commit();
    };

    float acc[2][8][4];
#pragma unroll
    for (int i = 0; i < 2; i++)
#pragma unroll
        for (int j = 0; j < 8; j++)
#pragma unroll
            for (int c = 0; c < 4; c++) acc[i][j][c] = 0.f;

    LOADA(0, 0);

    int nk = K / TBK;
    for (int kt = 0; kt < nk; kt++) {
        int cur = kt & 1;
        cp_wait0();
        __syncthreads();
        if (kt + 1 < nk) LOADA((kt + 1) * TBK, cur ^ 1);

#pragma unroll
        for (int k8 = 0; k8 < TBK; k8 += 8) {
            uint32_t af[2][4];
#pragma unroll
            for (int mf = 0; mf < 2; mf++) {
                int row = wm0 + mf * 16 + gID;
                af[mf][0] = As[cur][row][k8 + tIG];
                af[mf][1] = As[cur][row + 8][k8 + tIG];
                af[mf][2] = As[cur][row][k8 + tIG + 4];
                af[mf][3] = As[cur][row + 8][k8 + tIG + 4];
            }
#pragma unroll
            for (int nf = 0; nf < 8; nf++) {
                int col = wn0 + nf * 8 + gID;
                uint32_t b0 = Bs[cur][col][k8 + tIG];
                uint32_t b1 = Bs[cur][col][k8 + tIG + 4];
#pragma unroll
                for (int mf = 0; mf < 2; mf++) {
                    asm volatile(
                        "mma.sync.aligned.m16n8k8.row.col.f32.tf32.tf32.f32 "
                        "{%0,%1,%2,%3}, {%4,%5,%6,%7}, {%8,%9}, {%0,%1,%2,%3};"
                        : "+f"(acc[mf][nf][0]), "+f"(acc[mf][nf][1]),
                          "+f"(acc[mf][nf][2]), "+f"(acc[mf][nf][3])
                        : "r"(af[mf][0]), "r"(af[mf][1]), "r"(af[mf][2]), "r"(af[mf][3]),
                          "r"(b0), "r"(b1));
                }
            }
        }
    }

#pragma unroll
    for (int mf = 0; mf < 2; mf++) {
#pragma unroll
        for (int nf = 0; nf < 8; nf++) {
            int m = bm + wm0 + mf * 16 + gID;
            int n = bn + wn0 + nf * 8 + 2 * tIG;
            if (n < N) {
                float c0 = acc[mf][nf][0], c1 = acc[mf][nf][1];
                float c2 = acc[mf][nf][2], c3 = acc[mf][nf][3];
                if (resid) {
                    float2 ra = *(const float2*)(resid + (size_t)m * N + n);
                    float2 rb = *(const float2*)(resid + (size_t)(m + 8) * N + n);
                    c0 += ra.x; c1 += ra.y; c2 += rb.x; c3 += rb.y;
                }
                *(float2*)(C + (size_t)m * N + n)       = make_float2(c0, c1);
                *(float2*)(C + (size_t)(m + 8) * N + n) = make_float2(c2, c3);
            }
        }
    }
}

// ---------------------------------------------------------------------------
// Fused prep, 8-step chunks: one warp per (chain, chunk).
// elu+1, sum-norms, sigmoid(beta), and 64 WY cross terms via one 80-value
// butterfly. cross layout per chunk: [0..35] kq(i<=j), [36..63] -b_j*kk(i<j)
// ---------------------------------------------------------------------------
__global__ __launch_bounds__(128)
void prep_fused()
{
    int gw   = blockIdx.x * 4 + (threadIdx.x >> 5);   // 0 .. NCHAIN*NCH8-1
    int lane = threadIdx.x & 31;
    int ch   = gw >> 7;          // chain  (NCH8 = 128)
    int cu   = gw & 127;         // chunk
    int t0   = cu * CH8;
    int b    = ch >> 3, h = ch & 7;

    float eq[8], ek[8], vv[8], bta[8];
#pragma unroll
    for (int s = 0; s < 8; s++) {
        const float* base = g_qkvb + ((size_t)(t0 + s) * BSZ + b) * PROJ + h * 97;
        float q = base[lane], k = base[32 + lane];
        vv[s]  = base[64 + lane];
        bta[s] = base[96];
        eq[s] = q > 0.f ? q + 1.f : __expf(q);
        ek[s] = k > 0.f ? k + 1.f : __expf(k);
    }

    float r[80];
#pragma unroll
    for (int s = 0; s < 8; s++) { r[s] = eq[s]; r[8 + s] = ek[s]; }
#pragma unroll
    for (int i = 0; i < 8; i++)
#pragma unroll
        for (int j = 0; j < 8; j++)
            if (j >= i) r[16 + UTx(i, j)] = ek[i] * eq[j];
#pragma unroll
    for (int i = 0; i < 8; i++)
#pragma unroll
        for (int j = 0; j < 8; j++)
            if (j > i) r[52 + STx(i, j)] = ek[i] * ek[j];

#pragma unroll
    for (int o = 16; o > 0; o >>= 1) {
#pragma unroll
        for (int i = 0; i < 80; i++)
            r[i] += __shfl_xor_sync(0xffffffffu, r[i], o);
    }

    float rsq[8], rsk[8], be[8];
#pragma unroll
    for (int s = 0; s < 8; s++) {
        rsq[s] = 1.0f / (r[s] + 1e-5f);
        rsk[s] = 1.0f / (r[8 + s] + 1e-5f);
        be[s]  = 1.0f / (1.0f + __expf(-bta[s]));
    }

#pragma unroll
    for (int s = 0; s < 8; s++) {
        size_t oi = ((size_t)ch * SLEN + t0 + s) * DH + lane;
        g_qn[oi] = eq[s] * rsq[s];
        g_kn[oi] = ek[s] * rsk[s];
        g_vn[oi] = vv[s];
    }

#pragma unroll
    for (int i = 0; i < 8; i++)
#pragma unroll
        for (int j = 0; j < 8; j++)
            if (j >= i) r[16 + UTx(i, j)] *= rsk[i] * rsq[j];
#pragma unroll
    for (int i = 0; i < 8; i++)
#pragma unroll
        for (int j = 0; j < 8; j++)
            if (j > i) r[52 + STx(i, j)] *= -be[j] * rsk[i] * rsk[j];

    if (lane == 0) {
        size_t bb = (size_t)ch * SLEN + t0;
#pragma unroll
        for (int s = 0; s < 8; s++) g_beta[bb + s] = be[s];
        float4* o = (float4*)(g_cross + ((size_t)ch * NCH8 + cu) * 64);
#pragma unroll
        for (int u = 0; u < 16; u++)
            o[u] = make_float4(r[16 + 4 * u], r[17 + 4 * u], r[18 + 4 * u], r[19 + 4 * u]);
    }
}

// ---------------------------------------------------------------------------
// Delta-rule recurrence, WY chunk = 8, 4 warps per chain (column-split W).
// Thread (r,g): row r, cols [8g,8g+8). One interior barrier per 8 steps plus
// one end-of-refill-chunk barrier (protects the smem double buffers).
// ---------------------------------------------------------------------------
__global__ __launch_bounds__(128)
void rec_kernel(const float* __restrict__ state,
                float* __restrict__ out_fw, int write_fw)
{
    int chain = blockIdx.x;            // 0..127
    int b = chain >> 3, h = chain & 7;
    int tid = threadIdx.x;
    int r = tid & 31;
    int g = tid >> 5;

    u64t Wp[4];
    const u64t* st = (const u64t*)(state + ((size_t)chain * DH + r) * DH + g * 8);
#pragma unroll
    for (int j = 0; j < 4; j++) Wp[j] = st[j];

    __shared__ __align__(16) float sk[2][TCH * DH];
    __shared__ __align__(16) float sq[2][TCH * DH];
    __shared__ __align__(16) float sv[2][TCH * DH];
    __shared__ float sbeta[2][TCH];
    __shared__ __align__(16) float scr[2][128];       // 2 chunks x 64
    __shared__ float part[2][16][32][5];              // [sub][s:0-7 A,8-15 Q][row][g]

    const float* kb  = g_kn   + (size_t)chain * SLEN * DH;
    const float* qb  = g_qn   + (size_t)chain * SLEN * DH;
    const float* vb  = g_vn   + (size_t)chain * SLEN * DH;
    const float* bb  = g_beta + (size_t)chain * SLEN;
    const float* crb = g_cross + (size_t)chain * NCH8 * 64;

    auto REFILL = [&](int cc, int buf) {
        ((float4*)sk[buf])[tid] = ((const float4*)(kb + (size_t)cc * TCH * DH))[tid];
        ((float4*)sq[buf])[tid] = ((const float4*)(qb + (size_t)cc * TCH * DH))[tid];
        ((float4*)sv[buf])[tid] = ((const float4*)(vb + (size_t)cc * TCH * DH))[tid];
        if (tid < TCH) sbeta[buf][tid] = bb[cc * TCH + tid];
        scr[buf][tid] = crb[(size_t)cc * 128 + tid];
    };

    REFILL(0, 0);
    __syncthreads();

    const int NCC = SLEN / TCH;     // 64 refills, 2 chunks each
    for (int cc = 0; cc < NCC; cc++) {
        int buf = cc & 1;
        if (cc + 1 < NCC) REFILL(cc + 1, buf ^ 1);

#pragma unroll
        for (int sub = 0; sub < 2; sub++) {
            int tb = sub * CH8;
            int pc = sub;

            // 16 partial dots vs this thread's W col-slice
#pragma unroll
            for (int s = 0; s < 8; s++) {
                const u64t* kp = (const u64t*)&sk[buf][(tb + s) * DH + g * 8];
                const u64t* qp = (const u64t*)&sq[buf][(tb + s) * DH + g * 8];
                part[pc][s][r][g]     = dot8(Wp, kp);
                part[pc][8 + s][r][g] = dot8(Wp, qp);
            }
            __syncthreads();

            float A[8];
#pragma unroll
            for (int s = 0; s < 8; s++)
                A[s] = (part[pc][s][r][0] + part[pc][s][r][1]) +
                       (part[pc][s][r][2] + part[pc][s][r][3]);
            int j0 = 2 * g, j1 = 2 * g + 1;
            float Q0 = (part[pc][8 + j0][r][0] + part[pc][8 + j0][r][1]) +
                       (part[pc][8 + j0][r][2] + part[pc][8 + j0][r][3]);
            float Q1 = (part[pc][8 + j1][r][0] + part[pc][8 + j1][r][1]) +
                       (part[pc][8 + j1][r][2] + part[pc][8 + j1][r][3]);

            const float* cq = &scr[buf][sub * 64];
            const float* ck = cq + 36;

            float d[8];
#pragma unroll
            for (int j = 0; j < 8; j++) {
                float bej = sbeta[buf][tb + j];
                float t = fmaf(-bej, A[j], bej * sv[buf][(tb + j) * DH + r]);
#pragma unroll
                for (int i = 0; i < 7; i++)
                    if (i < j) t = fmaf(d[i], ck[STx(i, j)], t);
                d[j] = t;
            }

            // outputs: warp g emits steps j0, j1
            float o0 = Q0, o1 = Q1;
#pragma unroll
            for (int i = 0; i < 8; i++) {
                int base_i = i * (15 - i) / 2;
                if (i <= j0) o0 = fmaf(d[i], cq[base_i + j0], o0);
                if (i <= j1) o1 = fmaf(d[i], cq[base_i + j1], o1);
            }
            int tg = cc * TCH + tb;
            g_oseq[((size_t)(tg + j0) * BSZ + b) * IND + h * DH + r] = rnd_tf32(o0);
            g_oseq[((size_t)(tg + j1) * BSZ + b) * IND + h * DH + r] = rnd_tf32(o1);

            // rank-8 update on the local col-slice (reload k slices, broadcast LDS)
#pragma unroll
            for (int s = 0; s < 8; s++) {
                const u64t* kp = (const u64t*)&sk[buf][(tb + s) * DH + g * 8];
                u64t D = f2pack(d[s], d[s]);
#pragma unroll
                for (int j = 0; j < 4; j++) Wp[j] = ffma2(D, kp[j], Wp[j]);
            }
        }
        __syncthreads();   // close refill window: all reads of buf done
    }

    if (write_fw) {
        u64t* fw = (u64t*)(out_fw + ((size_t)chain * DH + r) * DH + g * 8);
#pragma unroll
        for (int j = 0; j < 4; j++) fw[j] = Wp[j];
    }
}

// ---------------------------------------------------------------------------
extern "C" void kernel_launch(void* const* d_in, const int* in_sizes, int n_in,
                              void* d_out, int out_size)
{
    const float* x        = (const float*)d_in[0];
    const float* state    = (const float*)d_in[1];
    const float* W_slow   = (const float*)d_in[2];
    const float* ln_gamma = (const float*)d_in[3];
    const float* ln_beta  = (const float*)d_in[4];
    const float* W_out    = (const float*)d_in[5];
    float* out = (float*)d_out;

    float* normed; cudaGetSymbolAddress((void**)&normed, g_normed);
    float* qkvb;   cudaGetSymbolAddress((void**)&qkvb,   g_qkvb);
    float* oseq;   cudaGetSymbolAddress((void**)&oseq,   g_oseq);
    float* wslow;  cudaGetSymbolAddress((void**)&wslow,  g_wslow_t);
    float* wout;   cudaGetSymbolAddress((void**)&wout,   g_wout_t);

    // 0) LN (tf32-rounded out) + weight rounding, fused
    ln_round_kernel<<<NTOK + RTOT / 256, IND>>>(x, ln_gamma, ln_beta, W_slow, W_out);

    // 1) qkvb = normed @ W_slow^T   [16384 x 776], tf32 TC + cp.async
    dim3 gB(NTOK / TBM, (PROJ + TBN - 1) / TBN);
    gemm_tf32<<<gB, 256>>>(normed, wslow, qkvb, NTOK, PROJ, IND, nullptr);

    // 2) fused prep (8-step WY chunks)
    prep_fused<<<NCHAIN * NCH8 / 4, 128>>>();

    // 3) delta-rule recurrence  (ncu capture lands here)
    int write_fw = (out_size >= (int)((size_t)NTOK * IND + FW_ELEMS)) ? 1 : 0;
    rec_kernel<<<NCHAIN, 128>>>(state, out + (size_t)NTOK * IND, write_fw);

    // 4) out = x + oseq @ W_out^T   [16384 x 256], tf32 TC (resid fp32)
    dim3 gD(NTOK / TBM, (IND + TBN - 1) / TBN);
    gemm_tf32<<<gD, 256>>>(oseq, wout, out, NTOK, IND, IND, x);
}

// round 10
// speedup vs baseline: 2.7950x; 1.0999x over previous
#include <cuda_runtime.h>
#include <cstdint>

#define SLEN 1024
#define BSZ  16
#define IND  256
#define NH   8
#define DH   32
#define PROJ 776              // NH*(3*DH+1)
#define NTOK (SLEN*BSZ)       // 16384
#define NCHAIN (BSZ*NH)       // 128
#define FW_ELEMS (NCHAIN*DH*DH)
#define TCH  32               // staged steps per refill (4 chunks of 8)
#define CH8  8                // WY chunk size
#define NCH8 (SLEN/CH8)       // 128 chunks per chain
#define RTOT (PROJ*IND + IND*IND)   // 264192 weight elems to round

// Scratch (static device globals; no runtime allocation)
__device__ __align__(16) float g_normed[(size_t)NTOK*IND];   // tf32-rounded
__device__ __align__(16) float g_qkvb[(size_t)NTOK*PROJ];
__device__ __align__(16) float g_oseq[(size_t)NTOK*IND];     // tf32-rounded
__device__ __align__(16) float g_kn[(size_t)NCHAIN*SLEN*DH];
__device__ __align__(16) float g_qn[(size_t)NCHAIN*SLEN*DH];
__device__ __align__(16) float g_vn[(size_t)NCHAIN*SLEN*DH];
__device__ __align__(16) float g_beta[(size_t)NCHAIN*SLEN];
__device__ __align__(16) float g_cross[(size_t)NCHAIN*NCH8*64];
__device__ __align__(16) float g_wslow_t[(size_t)PROJ*IND];  // tf32-rounded
__device__ __align__(16) float g_wout_t[(size_t)IND*IND];    // tf32-rounded

// ---------------------------------------------------------------------------
// helpers
// ---------------------------------------------------------------------------
typedef unsigned long long u64t;

__device__ __forceinline__ u64t f2pack(float lo, float hi) {
    u64t r; asm("mov.b64 %0, {%1, %2};" : "=l"(r) : "f"(lo), "f"(hi)); return r;
}
__device__ __forceinline__ void f2unpack(u64t v, float& lo, float& hi) {
    asm("mov.b64 {%0, %1}, %2;" : "=f"(lo), "=f"(hi) : "l"(v));
}
__device__ __forceinline__ u64t ffma2(u64t a, u64t b, u64t c) {
    u64t d; asm("fma.rn.f32x2 %0, %1, %2, %3;" : "=l"(d) : "l"(a), "l"(b), "l"(c)); return d;
}
__device__ __forceinline__ uint32_t to_tf32(float x) {
    uint32_t u; asm("cvt.rna.tf32.f32 %0, %1;" : "=r"(u) : "f"(x)); return u;
}
__device__ __forceinline__ float rnd_tf32(float x) {
    return __uint_as_float(to_tf32(x));
}
__device__ __forceinline__ uint32_t smem_u32(const void* p) {
    return (uint32_t)__cvta_generic_to_shared(p);
}
__device__ __forceinline__ void cp16(uint32_t d, const void* s, int ssz) {
    asm volatile("cp.async.ca.shared.global [%0], [%1], 16, %2;" :: "r"(d), "l"(s), "r"(ssz));
}
__device__ __forceinline__ void cp_commit() { asm volatile("cp.async.commit_group;" ::); }
__device__ __forceinline__ void cp_wait0()  { asm volatile("cp.async.wait_group 0;" ::); }

// 8-wide dot of packed slices (4 x f32x2)
__device__ __forceinline__ float dot8(const u64t* __restrict__ Wp,
                                      const u64t* __restrict__ vp) {
    u64t a = 0ull, b = 0ull;
    a = ffma2(Wp[0], vp[0], a); b = ffma2(Wp[1], vp[1], b);
    a = ffma2(Wp[2], vp[2], a); b = ffma2(Wp[3], vp[3], b);
    float x0, x1, y0, y1;
    f2unpack(a, x0, x1); f2unpack(b, y0, y1);
    return (x0 + y0) + (x1 + y1);
}

// upper-tri (i<=j) and strict (i<j) index maps over 8 steps
__host__ __device__ constexpr int UTx(int i, int j) { return i * (15 - i) / 2 + j; }
__host__ __device__ constexpr int STx(int i, int j) { return i * (13 - i) / 2 + j - 1; }

// ---------------------------------------------------------------------------
// Fused: LayerNorm (tf32-rounded output) + weight rounding
// ---------------------------------------------------------------------------
__global__ void ln_round_kernel(const float* __restrict__ x,
                                const float* __restrict__ gamma,
                                const float* __restrict__ beta,
                                const float* __restrict__ Wslow,
                                const float* __restrict__ Wout)
{
    int blk = blockIdx.x, tid = threadIdx.x;
    if (blk >= NTOK) {
        int i = (blk - NTOK) * 256 + tid;
        if (i < PROJ * IND)       g_wslow_t[i] = rnd_tf32(Wslow[i]);
        else if (i < RTOT)        g_wout_t[i - PROJ * IND] = rnd_tf32(Wout[i - PROJ * IND]);
        return;
    }
    float v = x[(size_t)blk * IND + tid];
    float s = v, s2 = v * v;
#pragma unroll
    for (int o = 16; o > 0; o >>= 1) {
        s  += __shfl_xor_sync(0xffffffffu, s,  o);
        s2 += __shfl_xor_sync(0xffffffffu, s2, o);
    }
    __shared__ float sh[2][8];
    int w = tid >> 5, l = tid & 31;
    if (l == 0) { sh[0][w] = s; sh[1][w] = s2; }
    __syncthreads();
    float ts = 0.f, ts2 = 0.f;
#pragma unroll
    for (int i = 0; i < 8; i++) { ts += sh[0][i]; ts2 += sh[1][i]; }
    float mu  = ts * (1.0f / IND);
    float var = ts2 * (1.0f / IND) - mu * mu;
    float rr  = rsqrtf(var + 1e-5f);
    g_normed[(size_t)blk * IND + tid] = rnd_tf32((v - mu) * rr * gamma[tid] + beta[tid]);
}

// ---------------------------------------------------------------------------
// TF32 tensor-core GEMM, cp.async streamed (operands pre-rounded to tf32)
// ---------------------------------------------------------------------------
#define TBM 128
#define TBN 128
#define TBK 16
#define TPAD 20

__global__ __launch_bounds__(256)
void gemm_tf32(const float* __restrict__ A, const float* __restrict__ B,
               float* __restrict__ C, int M, int N, int K,
               const float* __restrict__ resid)
{
    __shared__ uint32_t As[2][TBM][TPAD];
    __shared__ uint32_t Bs[2][TBN][TPAD];

    int bm = blockIdx.x * TBM;
    int bn = blockIdx.y * TBN;
    int tid = threadIdx.x;
    int wid = tid >> 5, lane = tid & 31;
    int warpM = wid & 3, warpN = wid >> 2;
    int gID = lane >> 2, tIG = lane & 3;
    int wm0 = warpM * 32, wn0 = warpN * 64;

    int f0 = tid,       r0 = f0 >> 2, kc0 = (f0 & 3) * 4;
    int f1 = tid + 256, r1 = f1 >> 2, kc1 = (f1 & 3) * 4;

    uint32_t aA[2], aA1[2], aB[2], aB1[2];
#pragma unroll
    for (int bf = 0; bf < 2; bf++) {
        aA[bf]  = smem_u32(&As[bf][r0][kc0]);
        aA1[bf] = smem_u32(&As[bf][r1][kc1]);
        aB[bf]  = smem_u32(&Bs[bf][r0][kc0]);
        aB1[bf] = smem_u32(&Bs[bf][r1][kc1]);
    }
    int bz0 = (bn + r0 < N) ? 16 : 0;
    int bz1 = (bn + r1 < N) ? 16 : 0;

    auto LOADA = [&](int k0, int bf) {
        cp16(aA[bf],  A + (size_t)(bm + r0) * K + k0 + kc0, 16);
        cp16(aA1[bf], A + (size_t)(bm + r1) * K + k0 + kc1, 16);
        cp16(aB[bf],  B + (size_t)(bn + r0) * K + k0 + kc0, bz0);
        cp16(aB1[bf], B + (size_t)(bn + r1) * K + k0 + kc1, bz1);
        cp_commit();
    };

    float acc[2][8][4];
#pragma unroll
    for (int i = 0; i < 2; i++)
#pragma unroll
        for (int j = 0; j < 8; j++)
#pragma unroll
            for (int c = 0; c < 4; c++) acc[i][j][c] = 0.f;

    LOADA(0, 0);

    int nk = K / TBK;
    for (int kt = 0; kt < nk; kt++) {
        int cur = kt & 1;
        cp_wait0();
        __syncthreads();
        if (kt + 1 < nk) LOADA((kt + 1) * TBK, cur ^ 1);

#pragma unroll
        for (int k8 = 0; k8 < TBK; k8 += 8) {
            uint32_t af[2][4];
#pragma unroll
            for (int mf = 0; mf < 2; mf++) {
                int row = wm0 + mf * 16 + gID;
                af[mf][0] = As[cur][row][k8 + tIG];
                af[mf][1] = As[cur][row + 8][k8 + tIG];
                af[mf][2] = As[cur][row][k8 + tIG + 4];
                af[mf][3] = As[cur][row + 8][k8 + tIG + 4];
            }
#pragma unroll
            for (int nf = 0; nf < 8; nf++) {
                int col = wn0 + nf * 8 + gID;
                uint32_t b0 = Bs[cur][col][k8 + tIG];
                uint32_t b1 = Bs[cur][col][k8 + tIG + 4];
#pragma unroll
                for (int mf = 0; mf < 2; mf++) {
                    asm volatile(
                        "mma.sync.aligned.m16n8k8.row.col.f32.tf32.tf32.f32 "
                        "{%0,%1,%2,%3}, {%4,%5,%6,%7}, {%8,%9}, {%0,%1,%2,%3};"
                        : "+f"(acc[mf][nf][0]), "+f"(acc[mf][nf][1]),
                          "+f"(acc[mf][nf][2]), "+f"(acc[mf][nf][3])
                        : "r"(af[mf][0]), "r"(af[mf][1]), "r"(af[mf][2]), "r"(af[mf][3]),
                          "r"(b0), "r"(b1));
                }
            }
        }
    }

#pragma unroll
    for (int mf = 0; mf < 2; mf++) {
#pragma unroll
        for (int nf = 0; nf < 8; nf++) {
            int m = bm + wm0 + mf * 16 + gID;
            int n = bn + wn0 + nf * 8 + 2 * tIG;
            if (n < N) {
                float c0 = acc[mf][nf][0], c1 = acc[mf][nf][1];
                float c2 = acc[mf][nf][2], c3 = acc[mf][nf][3];
                if (resid) {
                    float2 ra = *(const float2*)(resid + (size_t)m * N + n);
                    float2 rb = *(const float2*)(resid + (size_t)(m + 8) * N + n);
                    c0 += ra.x; c1 += ra.y; c2 += rb.x; c3 += rb.y;
                }
                *(float2*)(C + (size_t)m * N + n)       = make_float2(c0, c1);
                *(float2*)(C + (size_t)(m + 8) * N + n) = make_float2(c2, c3);
            }
        }
    }
}

// ---------------------------------------------------------------------------
// Fused prep, 8-step chunks: one warp per (chain, chunk).
// cross layout per chunk: [0..35] kq(i<=j), [36..63] -b_j*kk(i<j)
// ---------------------------------------------------------------------------
__global__ __launch_bounds__(128)
void prep_fused()
{
    int gw   = blockIdx.x * 4 + (threadIdx.x >> 5);   // 0 .. NCHAIN*NCH8-1
    int lane = threadIdx.x & 31;
    int ch   = gw >> 7;          // chain  (NCH8 = 128)
    int cu   = gw & 127;         // chunk
    int t0   = cu * CH8;
    int b    = ch >> 3, h = ch & 7;

    float eq[8], ek[8], vv[8], bta[8];
#pragma unroll
    for (int s = 0; s < 8; s++) {
        const float* base = g_qkvb + ((size_t)(t0 + s) * BSZ + b) * PROJ + h * 97;
        float q = base[lane], k = base[32 + lane];
        vv[s]  = base[64 + lane];
        bta[s] = base[96];
        eq[s] = q > 0.f ? q + 1.f : __expf(q);
        ek[s] = k > 0.f ? k + 1.f : __expf(k);
    }

    float r[80];
#pragma unroll
    for (int s = 0; s < 8; s++) { r[s] = eq[s]; r[8 + s] = ek[s]; }
#pragma unroll
    for (int i = 0; i < 8; i++)
#pragma unroll
        for (int j = 0; j < 8; j++)
            if (j >= i) r[16 + UTx(i, j)] = ek[i] * eq[j];
#pragma unroll
    for (int i = 0; i < 8; i++)
#pragma unroll
        for (int j = 0; j < 8; j++)
            if (j > i) r[52 + STx(i, j)] = ek[i] * ek[j];

#pragma unroll
    for (int o = 16; o > 0; o >>= 1) {
#pragma unroll
        for (int i = 0; i < 80; i++)
            r[i] += __shfl_xor_sync(0xffffffffu, r[i], o);
    }

    float rsq[8], rsk[8], be[8];
#pragma unroll
    for (int s = 0; s < 8; s++) {
        rsq[s] = 1.0f / (r[s] + 1e-5f);
        rsk[s] = 1.0f / (r[8 + s] + 1e-5f);
        be[s]  = 1.0f / (1.0f + __expf(-bta[s]));
    }

#pragma unroll
    for (int s = 0; s < 8; s++) {
        size_t oi = ((size_t)ch * SLEN + t0 + s) * DH + lane;
        g_qn[oi] = eq[s] * rsq[s];
        g_kn[oi] = ek[s] * rsk[s];
        g_vn[oi] = vv[s];
    }

#pragma unroll
    for (int i = 0; i < 8; i++)
#pragma unroll
        for (int j = 0; j < 8; j++)
            if (j >= i) r[16 + UTx(i, j)] *= rsk[i] * rsq[j];
#pragma unroll
    for (int i = 0; i < 8; i++)
#pragma unroll
        for (int j = 0; j < 8; j++)
            if (j > i) r[52 + STx(i, j)] *= -be[j] * rsk[i] * rsk[j];

    if (lane == 0) {
        size_t bb = (size_t)ch * SLEN + t0;
#pragma unroll
        for (int s = 0; s < 8; s++) g_beta[bb + s] = be[s];
        float4* o = (float4*)(g_cross + ((size_t)ch * NCH8 + cu) * 64);
#pragma unroll
        for (int u = 0; u < 16; u++)
            o[u] = make_float4(r[16 + 4 * u], r[17 + 4 * u], r[18 + 4 * u], r[19 + 4 * u]);
    }
}

// ---------------------------------------------------------------------------
// Delta-rule recurrence, WY chunk = 8, 8 WARPS per chain.
// Warp w (0..7): col-group g = w&3 (cols [8g,8g+8)), role = w>>2
//   role 0 -> k-dots (A), role 1 -> q-dots (Q). Both roles hold identical
//   copies of the W col-slice and apply identical rank-8 updates.
// All warps redundantly run the scattered-form delta chain (depth 8 fma).
// Warp w emits output step w. One barrier per 8-step chunk.
// ---------------------------------------------------------------------------
__global__ __launch_bounds__(256)
void rec_kernel(const float* __restrict__ state,
                float* __restrict__ out_fw, int write_fw)
{
    int chain = blockIdx.x;            // 0..127
    int b = chain >> 3, h = chain & 7;
    int tid = threadIdx.x;
    int r = tid & 31;                  // row
    int w = tid >> 5;                  // warp 0..7
    int g = w & 3;                     // column group
    int isQ = w >> 2;                  // role

    u64t Wp[4];
    const u64t* st = (const u64t*)(state + ((size_t)chain * DH + r) * DH + g * 8);
#pragma unroll
    for (int j = 0; j < 4; j++) Wp[j] = st[j];

    __shared__ __align__(16) float sk[2][TCH * DH];
    __shared__ __align__(16) float sq[2][TCH * DH];
    __shared__ __align__(16) float sv[2][TCH * DH];
    __shared__ float sbeta[2][TCH];
    __shared__ __align__(16) float scr[2][256];       // 4 chunks x 64
    __shared__ float part[2][16][32][5];              // [pc][s:0-7 A,8-15 Q][row][g]

    const float* kb  = g_kn   + (size_t)chain * SLEN * DH;
    const float* qb  = g_qn   + (size_t)chain * SLEN * DH;
    const float* vb  = g_vn   + (size_t)chain * SLEN * DH;
    const float* bb  = g_beta + (size_t)chain * SLEN;
    const float* crb = g_cross + (size_t)chain * NCH8 * 64;

    auto REFILL = [&](int cc, int buf) {
        ((float4*)sk[buf])[tid] = ((const float4*)(kb + (size_t)cc * TCH * DH))[tid];
        ((float4*)sq[buf])[tid] = ((const float4*)(qb + (size_t)cc * TCH * DH))[tid];
        ((float4*)sv[buf])[tid] = ((const float4*)(vb + (size_t)cc * TCH * DH))[tid];
        if (tid < TCH) sbeta[buf][tid] = bb[cc * TCH + tid];
        scr[buf][tid] = crb[(size_t)cc * 256 + tid];
    };

    REFILL(0, 0);
    __syncthreads();

    const int NCC = SLEN / TCH;     // 32 refills, 4 chunks each
    for (int cc = 0; cc < NCC; cc++) {
        int buf = cc & 1;
        if (cc + 1 < NCC) REFILL(cc + 1, buf ^ 1);

#pragma unroll
        for (int sub = 0; sub < TCH / CH8; sub++) {
            int tb = sub * CH8;
            int pc = sub & 1;

            // role-specialized dots: 8 per warp
            const float* src = isQ ? &sq[buf][0] : &sk[buf][0];
#pragma unroll
            for (int s = 0; s < 8; s++) {
                const u64t* vp = (const u64t*)&src[(tb + s) * DH + g * 8];
                part[pc][isQ * 8 + s][r][g] = dot8(Wp, vp);
            }
            __syncthreads();

            float A[8];
#pragma unroll
            for (int s = 0; s < 8; s++)
                A[s] = (part[pc][s][r][0] + part[pc][s][r][1]) +
                       (part[pc][s][r][2] + part[pc][s][r][3]);

            const float* cq = &scr[buf][sub * 64];
            const float* ck = cq + 36;

            // scattered-form forward substitution (serial depth = 8 fma)
            float acc[8];
#pragma unroll
            for (int j = 0; j < 8; j++) {
                float bej = sbeta[buf][tb + j];
                acc[j] = fmaf(-bej, A[j], bej * sv[buf][(tb + j) * DH + r]);
            }
            float d[8];
#pragma unroll
            for (int i = 0; i < 8; i++) {
                d[i] = acc[i];
#pragma unroll
                for (int j = 0; j < 8; j++)
                    if (j > i) acc[j] = fmaf(d[i], ck[STx(i, j)], acc[j]);
            }

            // output: warp w emits step w
            float Qw = (part[pc][8 + w][r][0] + part[pc][8 + w][r][1]) +
                       (part[pc][8 + w][r][2] + part[pc][8 + w][r][3]);
#pragma unroll
            for (int i = 0; i < 8; i++)
                if (i <= w) Qw = fmaf(d[i], cq[UTx(i, w)], Qw);
            int tg = cc * TCH + tb;
            g_oseq[((size_t)(tg + w) * BSZ + b) * IND + h * DH + r] = rnd_tf32(Qw);

            // rank-8 update on the local col-slice (both roles, identical)
#pragma unroll
            for (int s = 0; s < 8; s++) {
                const u64t* kp = (const u64t*)&sk[buf][(tb + s) * DH + g * 8];
                u64t D = f2pack(d[s], d[s]);
#pragma unroll
                for (int j = 0; j < 4; j++) Wp[j] = ffma2(D, kp[j], Wp[j]);
            }
        }
        __syncthreads();   // close refill window for buf
    }

    if (write_fw && isQ == 0) {
        u64t* fw = (u64t*)(out_fw + ((size_t)chain * DH + r) * DH + g * 8);
#pragma unroll
        for (int j = 0; j < 4; j++) fw[j] = Wp[j];
    }
}

// ---------------------------------------------------------------------------
extern "C" void kernel_launch(void* const* d_in, const int* in_sizes, int n_in,
                              void* d_out, int out_size)
{
    const float* x        = (const float*)d_in[0];
    const float* state    = (const float*)d_in[1];
    const float* W_slow   = (const float*)d_in[2];
    const float* ln_gamma = (const float*)d_in[3];
    const float* ln_beta  = (const float*)d_in[4];
    const float* W_out    = (const float*)d_in[5];
    float* out = (float*)d_out;

    float* normed; cudaGetSymbolAddress((void**)&normed, g_normed);
    float* qkvb;   cudaGetSymbolAddress((void**)&qkvb,   g_qkvb);
    float* oseq;   cudaGetSymbolAddress((void**)&oseq,   g_oseq);
    float* wslow;  cudaGetSymbolAddress((void**)&wslow,  g_wslow_t);
    float* wout;   cudaGetSymbolAddress((void**)&wout,   g_wout_t);

    // 0) LN (tf32-rounded out) + weight rounding, fused
    ln_round_kernel<<<NTOK + RTOT / 256, IND>>>(x, ln_gamma, ln_beta, W_slow, W_out);

    // 1) qkvb = normed @ W_slow^T   [16384 x 776], tf32 TC + cp.async
    dim3 gB(NTOK / TBM, (PROJ + TBN - 1) / TBN);
    gemm_tf32<<<gB, 256>>>(normed, wslow, qkvb, NTOK, PROJ, IND, nullptr);

    // 2) fused prep (8-step WY chunks)
    prep_fused<<<NCHAIN * NCH8 / 4, 128>>>();

    // 3) delta-rule recurrence (8 warps/chain, A/Q specialization)
    int write_fw = (out_size >= (int)((size_t)NTOK * IND + FW_ELEMS)) ? 1 : 0;
    rec_kernel<<<NCHAIN, 256>>>(state, out + (size_t)NTOK * IND, write_fw);

    // 4) out = x + oseq @ W_out^T   [16384 x 256], tf32 TC (resid fp32)
    dim3 gD(NTOK / TBM, (IND + TBN - 1) / TBN);
    gemm_tf32<<<gD, 256>>>(oseq, wout, out, NTOK, IND, IND, x);
}